// round 12
// baseline (speedup 1.0000x reference)
#include <cuda_runtime.h>
#include <cuda_bf16.h>
#include <math.h>
#include <stdint.h>

#define NN    2048
#define BATCH 16
#define DEMB  10
#define CTOT  128
#define CO    64
#define BC    (BATCH*CTOT)   // 2048
#define BZ    (BATCH*CO)     // 1024
#define KC    (3*CTOT)       // 384
#define JG    (KC*CTOT)      // 49152
#define JU    (KC*CO)        // 24576

// ---------------- device scratch ----------------
__device__ float g_IAS[(size_t)NN*BC];
__device__ float g_XG1[(size_t)NN*BC];
__device__ float g_XG2[(size_t)NN*BC];
__device__ float g_Z  [(size_t)NN*BZ];
__device__ float g_ZG1[(size_t)NN*BZ];
__device__ float g_ZG2[(size_t)NN*BZ];
__device__ float g_Wg [(size_t)NN*JG];
__device__ float g_Wu [(size_t)NN*JU];
__device__ float g_ACC1[(size_t)NN*BC];   // gate partial acc
__device__ float g_ACC2[(size_t)NN*BZ];   // upd partial acc
__device__ __align__(256) __nv_bfloat16 g_Shi[(size_t)NN*NN];
__device__ __align__(256) __nv_bfloat16 g_Slo[(size_t)NN*NN];
__device__ __align__(256) __nv_bfloat16 g_TaH[(size_t)NN*NN];
__device__ __align__(256) __nv_bfloat16 g_TaL[(size_t)NN*NN];
__device__ __align__(256) __nv_bfloat16 g_TbH[(size_t)NN*NN];
__device__ __align__(256) __nv_bfloat16 g_TbL[(size_t)NN*NN];

// ---------------- pickers ----------------
__device__ __forceinline__ const float* pickIn(int id){
  switch(id){ case 0: return g_IAS; case 1: return g_XG1; case 2: return g_XG2;
              case 3: return g_Z;   case 4: return g_ZG1; }
  return g_IAS;
}
__device__ __forceinline__ float* pickOut(int id){
  switch(id){ case 1: return g_XG1; case 2: return g_XG2;
              case 4: return g_ZG1; case 5: return g_ZG2; }
  return g_XG1;
}
__device__ __forceinline__ __nv_bfloat16* pickBF(int id){
  switch(id){ case 0: return g_TaH; case 1: return g_TaL;
              case 2: return g_TbH; case 3: return g_TbL; }
  return g_TaH;
}

// ---------------- warp reductions ----------------
__device__ __forceinline__ float warpMax(float v){
  #pragma unroll
  for(int o=16;o;o>>=1) v = fmaxf(v, __shfl_xor_sync(0xffffffffu, v, o));
  return v;
}
__device__ __forceinline__ float warpSum(float v){
  #pragma unroll
  for(int o=16;o;o>>=1) v += __shfl_xor_sync(0xffffffffu, v, o);
  return v;
}

// ---------------- PTX helpers ----------------
__device__ __forceinline__ uint32_t smem_u32(const void* p){
  uint32_t a;
  asm("{ .reg .u64 t; cvta.to.shared.u64 t, %1; cvt.u32.u64 %0, t; }" : "=r"(a) : "l"(p));
  return a;
}
__device__ __forceinline__ void cp16(uint32_t s, const void* g){
  asm volatile("cp.async.cg.shared.global [%0], [%1], 16;" :: "r"(s), "l"(g) : "memory");
}
__device__ __forceinline__ void cp_commit(){ asm volatile("cp.async.commit_group;" ::: "memory"); }
__device__ __forceinline__ void ldsm_x4(uint32_t* r, uint32_t a){
  asm volatile("ldmatrix.sync.aligned.m8n8.x4.shared.b16 {%0,%1,%2,%3}, [%4];"
    : "=r"(r[0]),"=r"(r[1]),"=r"(r[2]),"=r"(r[3]) : "r"(a));
}
__device__ __forceinline__ void mma16816(float* d, const uint32_t* a, const uint32_t* b){
  asm volatile("mma.sync.aligned.m16n8k16.row.col.f32.bf16.bf16.f32 "
    "{%0,%1,%2,%3}, {%4,%5,%6,%7}, {%8,%9}, {%0,%1,%2,%3};"
    : "+f"(d[0]),"+f"(d[1]),"+f"(d[2]),"+f"(d[3])
    : "r"(a[0]),"r"(a[1]),"r"(a[2]),"r"(a[3]), "r"(b[0]),"r"(b[1]));
}

// ---------------- K1: S row softmax -> bf16 hi/lo ----------------
__global__ void __launch_bounds__(256) k_supports(const float* __restrict__ E){
  __shared__ float sh[8];
  __shared__ float bcast;
  int row = blockIdx.x, tid = threadIdx.x;
  float Er[DEMB];
  #pragma unroll
  for(int d=0; d<DEMB; d++) Er[d] = E[row*DEMB + d];
  float a[8], m = -1e30f;
  #pragma unroll
  for(int q=0; q<8; q++){
    int col = tid + q*256;
    const float* Ec = E + (size_t)col*DEMB;
    float s = 0.f;
    #pragma unroll
    for(int d=0; d<DEMB; d++) s += Er[d]*Ec[d];
    s = fmaxf(s, 0.f);
    a[q] = s; m = fmaxf(m, s);
  }
  m = warpMax(m);
  if((tid&31)==0) sh[tid>>5] = m;
  __syncthreads();
  if(tid<32){ float t = (tid<8)? sh[tid] : -1e30f; t = warpMax(t); if(tid==0) bcast = t; }
  __syncthreads();
  m = bcast;
  float ssum = 0.f;
  #pragma unroll
  for(int q=0; q<8; q++){ a[q] = expf(a[q]-m); ssum += a[q]; }
  ssum = warpSum(ssum);
  __syncthreads();
  if((tid&31)==0) sh[tid>>5] = ssum;
  __syncthreads();
  if(tid<32){ float t = (tid<8)? sh[tid] : 0.f; t = warpSum(t); if(tid==0) bcast = t; }
  __syncthreads();
  float inv = 1.f/bcast;
  #pragma unroll
  for(int q=0; q<8; q++){
    float v = a[q]*inv;
    __nv_bfloat16 hi = __float2bfloat16(v);
    __nv_bfloat16 lo = __float2bfloat16(v - __bfloat162float(hi));
    size_t o = (size_t)row*NN + tid + q*256;
    g_Shi[o] = hi; g_Slo[o] = lo;
  }
}

// ---------------- K2: pack IAS ----------------
__global__ void __launch_bounds__(256) k_pack(const float* __restrict__ x,
                                              const float* __restrict__ st){
  int t = blockIdx.x*256 + threadIdx.x;
  int e = t*4;
  int n = e >> 11;
  int r = e & 2047;
  int b = r >> 7;
  int c = r & 127;
  float4 v;
  if (c < 64) v = *(const float4*)(x  + ((size_t)b*NN + n)*64 + c);
  else        v = *(const float4*)(st + ((size_t)b*NN + n)*64 + (c-64));
  *(float4*)(g_IAS + e) = v;
}

// -------- convert+transpose fp32 [2048 x W] -> bf16 hi/lo [W x 2048] --------
__global__ void __launch_bounds__(256) k_cvtT(int srcId, int W, int dstHi){
  const float* src = pickIn(srcId);
  __nv_bfloat16* dH = pickBF(dstHi);
  __nv_bfloat16* dL = pickBF(dstHi+1);
  __shared__ float t[32][33];
  int tx = threadIdx.x & 31, ty = threadIdx.x >> 5;
  int c0 = blockIdx.x*32, r0 = blockIdx.y*32;
  #pragma unroll
  for(int j=0;j<4;j++)
    t[ty+8*j][tx] = src[(size_t)(r0+ty+8*j)*W + c0+tx];
  __syncthreads();
  #pragma unroll
  for(int j=0;j<4;j++){
    float v = t[tx][ty+8*j];
    __nv_bfloat16 hi = __float2bfloat16(v);
    __nv_bfloat16 lo = __float2bfloat16(v - __bfloat162float(hi));
    size_t o = (size_t)(c0+ty+8*j)*NN + r0 + tx;
    dH[o] = hi; dL[o] = lo;
  }
}

// ---------------- K5: wcombine (float4) ----------------
__global__ void __launch_bounds__(256) k_wcombine(const float* __restrict__ E,
                                                  const float* __restrict__ wp,
                                                  int J, int which){
  float* out = which ? g_Wu : g_Wg;
  int j  = (blockIdx.x*256 + threadIdx.x)*4;
  int n0 = blockIdx.y*32;
  float4 w[DEMB];
  #pragma unroll
  for(int d=0; d<DEMB; d++) w[d] = *(const float4*)(wp + (size_t)d*J + j);
  __shared__ float Es[32*DEMB];
  for(int t=threadIdx.x; t<32*DEMB; t+=256) Es[t] = E[n0*DEMB + t];
  __syncthreads();
  #pragma unroll 2
  for(int nn=0; nn<32; nn++){
    float4 a = make_float4(0.f,0.f,0.f,0.f);
    #pragma unroll
    for(int d=0; d<DEMB; d++){
      float e = Es[nn*DEMB+d];
      a.x += e*w[d].x; a.y += e*w[d].y; a.z += e*w[d].z; a.w += e*w[d].w;
    }
    *(float4*)(out + (size_t)(n0+nn)*J + j) = a;
  }
}

// ---------------- HMMA bf16x3 GEMM (R6-best config) ----------------
#define PITCH    48

template<int MODE, int WRITE_T, int TM>
__global__ void __launch_bounds__(256,2) mma_gemm(int cId, int dId, int Ncols,
                                                  int bHiId, int tHiId){
  constexpr int WM   = (TM == 128) ? 4 : 2;
  constexpr int WN   = 8 / WM;
  constexpr int NT   = (128 / WN) / 8;
  constexpr int NTP  = NT / 2;
  constexpr int A_T  = TM * PITCH;
  constexpr int B_T  = 128 * PITCH;
  constexpr int STG  = 2*A_T + 2*B_T;
  constexpr int NTRANS = (2*TM + 2*128) * 2;

  extern __shared__ char smem[];
  float*       C = pickOut(cId);
  const float* D = pickIn(dId);
  const __nv_bfloat16* Bh = pickBF(bHiId);
  const __nv_bfloat16* Bl = pickBF(bHiId+1);
  const uint32_t sb = smem_u32(smem);
  const int tid = threadIdx.x, wid = tid >> 5, lane = tid & 31;
  const int warpM = wid % WM, warpN = wid / WM;
  const size_t row0 = (size_t)blockIdx.y * TM;
  const size_t n0   = (size_t)blockIdx.x * 128;

  float acc[2][NT][4];
  #pragma unroll
  for(int m=0;m<2;m++)
    #pragma unroll
    for(int n=0;n<NT;n++)
      #pragma unroll
      for(int q=0;q<4;q++) acc[m][n][q] = 0.f;

  auto issue = [&](int c){
    const size_t kb = (size_t)c * 16;
    const uint32_t bo = sb + (uint32_t)(c & 3) * STG;
    #pragma unroll
    for(int u = 0; u < NTRANS/256; u++){
      int e  = tid + u*256;
      int h  = e & 1;
      int rr = e >> 1;
      if(rr < TM){
        cp16(bo + rr*PITCH + h*16, g_Shi + (row0 + rr)*(size_t)NN + kb + h*8);
      } else if(rr < 2*TM){
        int r = rr - TM;
        cp16(bo + A_T + r*PITCH + h*16, g_Slo + (row0 + r)*(size_t)NN + kb + h*8);
      } else if(rr < 2*TM + 128){
        int r = rr - 2*TM;
        cp16(bo + 2*A_T + r*PITCH + h*16, Bh + (n0 + r)*(size_t)NN + kb + h*8);
      } else {
        int r = rr - 2*TM - 128;
        cp16(bo + 2*A_T + B_T + r*PITCH + h*16, Bl + (n0 + r)*(size_t)NN + kb + h*8);
      }
    }
    cp_commit();
  };

  issue(0); issue(1); issue(2);

  const uint32_t aoff = (uint32_t)((warpM*32 + (lane & 15))*PITCH + (lane >> 4)*16);
  const uint32_t boff = (uint32_t)(2*A_T + (warpN*(NT*8) + ((lane >> 4) & 1)*8 + (lane & 7))*PITCH
                                   + ((lane >> 3) & 1)*16);

  for(int c=0; c<128; c++){
    if(c <= 125)      asm volatile("cp.async.wait_group 2;" ::: "memory");
    else if(c == 126) asm volatile("cp.async.wait_group 1;" ::: "memory");
    else              asm volatile("cp.async.wait_group 0;" ::: "memory");
    __syncthreads();
    if(c + 3 < 128) issue(c+3);

    const uint32_t bo = sb + (uint32_t)(c & 3) * STG;
    uint32_t afH[2][4], afL[2][4];
    #pragma unroll
    for(int mt=0; mt<2; mt++){
      uint32_t ad = bo + aoff + (uint32_t)(mt*16*PITCH);
      ldsm_x4(afH[mt], ad);
      ldsm_x4(afL[mt], ad + A_T);
    }
    #pragma unroll
    for(int ntp=0; ntp<NTP; ntp++){
      uint32_t bd = bo + boff + (uint32_t)(ntp*16*PITCH);
      uint32_t bH[4], bL[4];
      ldsm_x4(bH, bd);
      ldsm_x4(bL, bd + B_T);
      mma16816(acc[0][2*ntp],   afH[0], bH);
      mma16816(acc[1][2*ntp],   afH[1], bH);
      mma16816(acc[0][2*ntp+1], afH[0], bH+2);
      mma16816(acc[1][2*ntp+1], afH[1], bH+2);
      mma16816(acc[0][2*ntp],   afH[0], bL);
      mma16816(acc[1][2*ntp],   afH[1], bL);
      mma16816(acc[0][2*ntp+1], afH[0], bL+2);
      mma16816(acc[1][2*ntp+1], afH[1], bL+2);
      mma16816(acc[0][2*ntp],   afL[0], bH);
      mma16816(acc[1][2*ntp],   afL[1], bH);
      mma16816(acc[0][2*ntp+1], afL[0], bH+2);
      mma16816(acc[1][2*ntp+1], afL[1], bH+2);
    }
  }

  // ---------------- epilogue ----------------
  const int g = lane >> 2, tg = lane & 3;
  #pragma unroll
  for(int mt=0; mt<2; mt++){
    size_t r0g = row0 + warpM*32 + mt*16 + g;
    #pragma unroll
    for(int nt=0; nt<NT; nt++){
      size_t col = n0 + warpN*(NT*8) + nt*8 + tg*2;
      size_t o0 = r0g      *(size_t)Ncols + col;
      size_t o1 = (r0g + 8)*(size_t)Ncols + col;
      float2 v0 = make_float2(acc[mt][nt][0], acc[mt][nt][1]);
      float2 v1 = make_float2(acc[mt][nt][2], acc[mt][nt][3]);
      if(MODE == 1){
        float2 d0 = *(const float2*)(D + o0);
        float2 d1 = *(const float2*)(D + o1);
        v0.x = 2.f*v0.x - d0.x; v0.y = 2.f*v0.y - d0.y;
        v1.x = 2.f*v1.x - d1.x; v1.y = 2.f*v1.y - d1.y;
      }
      *(float2*)(C + o0) = v0;
      *(float2*)(C + o1) = v1;
    }
  }

  if(WRITE_T){
    __nv_bfloat16* TH = pickBF(tHiId);
    __nv_bfloat16* TL = pickBF(tHiId+1);
    float* tile = (float*)smem;          // [TM][132]
    __syncthreads();
    #pragma unroll
    for(int mt=0; mt<2; mt++){
      int rr = warpM*32 + mt*16 + g;
      #pragma unroll
      for(int nt=0; nt<NT; nt++){
        int cc = warpN*(NT*8) + nt*8 + tg*2;
        tile[rr*132 + cc]         = acc[mt][nt][0];
        tile[rr*132 + cc + 1]     = acc[mt][nt][1];
        tile[(rr+8)*132 + cc]     = acc[mt][nt][2];
        tile[(rr+8)*132 + cc + 1] = acc[mt][nt][3];
      }
    }
    __syncthreads();
    int c0 = tid >> 1, half = tid & 1;
    size_t baseO = (size_t)(n0 + c0)*NN + row0 + half*(TM/2);
    #pragma unroll
    for(int ch=0; ch<TM/16; ch++){
      __nv_bfloat16 hb[8], lb8[8];
      #pragma unroll
      for(int e=0; e<8; e++){
        float v = tile[(half*(TM/2) + ch*8 + e)*132 + c0];
        __nv_bfloat16 hi = __float2bfloat16(v);
        hb[e] = hi;
        lb8[e] = __float2bfloat16(v - __bfloat162float(hi));
      }
      *(uint4*)(TH + baseO + ch*8) = *(uint4*)hb;
      *(uint4*)(TL + baseO + ch*8) = *(uint4*)lb8;
    }
  }
}

#define SM_128  (4*(2*(128*PITCH) + 2*(128*PITCH)))   // 98304
#define SM_64   (4*(2*(64*PITCH)  + 2*(128*PITCH)))   // 73728

// ---------------- gateA: bias + k=0,1 terms -> g_ACC1 ----------------
__global__ void __launch_bounds__(256) k_gateA(const float* __restrict__ E,
                                               const float* __restrict__ gbp){
  __shared__ float Xs[2*2048];
  __shared__ float bias[CTOT];
  int n = blockIdx.x, tid = threadIdx.x;
  for(int t=tid; t<512; t+=256){
    ((float4*)Xs)[t]        = ((const float4*)(g_IAS + (size_t)n*BC))[t];
    ((float4*)(Xs+2048))[t] = ((const float4*)(g_XG1 + (size_t)n*BC))[t];
  }
  if(tid < CTOT){
    float b = 0.f;
    #pragma unroll
    for(int d=0; d<DEMB; d++) b += E[n*DEMB + d]*gbp[d*CTOT + tid];
    bias[tid] = b;
  }
  __syncthreads();

  int oq = (tid & 31)*4;
  int b0 = (tid >> 5)*2, b1 = b0 + 1;
  float acc[2][4];
  #pragma unroll
  for(int q=0;q<4;q++){ acc[0][q] = bias[oq+q]; acc[1][q] = bias[oq+q]; }

  const float* W = g_Wg + (size_t)n*JG + oq;
  #pragma unroll
  for(int k=0; k<2; k++){
    const float* Xk0 = Xs + k*2048 + b0*CTOT;
    const float* Xk1 = Xs + k*2048 + b1*CTOT;
    const float* Wk  = W + (size_t)k*128*CTOT;
    #pragma unroll 8
    for(int i=0; i<128; i++){
      float4 w4 = *(const float4*)(Wk + (size_t)i*CTOT);
      float x0 = Xk0[i], x1 = Xk1[i];
      acc[0][0] += x0*w4.x; acc[0][1] += x0*w4.y; acc[0][2] += x0*w4.z; acc[0][3] += x0*w4.w;
      acc[1][0] += x1*w4.x; acc[1][1] += x1*w4.y; acc[1][2] += x1*w4.z; acc[1][3] += x1*w4.w;
    }
  }
  *(float4*)(g_ACC1 + (size_t)n*BC + b0*CTOT + oq) = make_float4(acc[0][0],acc[0][1],acc[0][2],acc[0][3]);
  *(float4*)(g_ACC1 + (size_t)n*BC + b1*CTOT + oq) = make_float4(acc[1][0],acc[1][1],acc[1][2],acc[1][3]);
}

// ---------------- gateB: k=2 + sigmoid + linear -> g_Z ----------------
__global__ void __launch_bounds__(256) k_gateB(const float* __restrict__ lw,
                                               const float* __restrict__ lb){
  __shared__ float smA[128*68];        // phase1: XG2 (2048 fl); phase2: lwT
  __shared__ float ysig[BATCH*CTOT];
  int n = blockIdx.x, tid = threadIdx.x;

  float* Xs = smA;
  for(int t=tid; t<512; t+=256)
    ((float4*)Xs)[t] = ((const float4*)(g_XG2 + (size_t)n*BC))[t];
  __syncthreads();

  int oq = (tid & 31)*4;
  int b0 = (tid >> 5)*2, b1 = b0 + 1;
  float acc[2][4];
  {
    float4 a0 = *(const float4*)(g_ACC1 + (size_t)n*BC + b0*CTOT + oq);
    float4 a1 = *(const float4*)(g_ACC1 + (size_t)n*BC + b1*CTOT + oq);
    acc[0][0]=a0.x; acc[0][1]=a0.y; acc[0][2]=a0.z; acc[0][3]=a0.w;
    acc[1][0]=a1.x; acc[1][1]=a1.y; acc[1][2]=a1.z; acc[1][3]=a1.w;
  }
  const float* Wk = g_Wg + (size_t)n*JG + (size_t)2*128*CTOT + oq;
  const float* Xk0 = Xs + b0*CTOT;
  const float* Xk1 = Xs + b1*CTOT;
  #pragma unroll 8
  for(int i=0; i<128; i++){
    float4 w4 = *(const float4*)(Wk + (size_t)i*CTOT);
    float x0 = Xk0[i], x1 = Xk1[i];
    acc[0][0] += x0*w4.x; acc[0][1] += x0*w4.y; acc[0][2] += x0*w4.z; acc[0][3] += x0*w4.w;
    acc[1][0] += x1*w4.x; acc[1][1] += x1*w4.y; acc[1][2] += x1*w4.z; acc[1][3] += x1*w4.w;
  }
  #pragma unroll
  for(int bb=0; bb<2; bb++){
    float4 v;
    v.x = 1.f/(1.f + expf(-acc[bb][0]));
    v.y = 1.f/(1.f + expf(-acc[bb][1]));
    v.z = 1.f/(1.f + expf(-acc[bb][2]));
    v.w = 1.f/(1.f + expf(-acc[bb][3]));
    *(float4*)(ysig + (b0+bb)*CTOT + oq) = v;
  }
  __syncthreads();

  float* lwT = smA;
  for(int t=tid; t<CO*CTOT; t+=256){ int c = t>>7, oo = t&127; lwT[oo*68 + c] = lw[t]; }
  __syncthreads();

  int c4  = (tid & 15)*4;
  int bg  = tid >> 4;
  float acc2[4];
  #pragma unroll
  for(int q=0;q<4;q++) acc2[q] = lb[c4+q];
  const float* Ys = ysig + bg*CTOT;
  #pragma unroll 8
  for(int o2=0; o2<CTOT; o2++){
    float4 w4 = *(const float4*)(lwT + o2*68 + c4);
    float y = Ys[o2];
    acc2[0] += y*w4.x; acc2[1] += y*w4.y; acc2[2] += y*w4.z; acc2[3] += y*w4.w;
  }
  *(float4*)(g_Z + (size_t)n*BZ + bg*CO + c4) = make_float4(acc2[0],acc2[1],acc2[2],acc2[3]);
}

// ---------------- updA: bias + x-half terms -> g_ACC2 ----------------
__global__ void __launch_bounds__(256) k_updA(const float* __restrict__ E,
                                              const float* __restrict__ ubp){
  __shared__ float Xs[3*1024];
  __shared__ float bias[CO];
  int n = blockIdx.x, tid = threadIdx.x;
  {
    const float* s0 = g_IAS + (size_t)n*BC;
    const float* s1 = g_XG1 + (size_t)n*BC;
    const float* s2 = g_XG2 + (size_t)n*BC;
    int b = tid >> 4, f = (tid & 15)*4;
    ((float4*)(Xs       ))[tid] = *(const float4*)(s0 + b*CTOT + f);
    ((float4*)(Xs + 1024))[tid] = *(const float4*)(s1 + b*CTOT + f);
    ((float4*)(Xs + 2048))[tid] = *(const float4*)(s2 + b*CTOT + f);
  }
  if(tid < CO){
    float b = 0.f;
    #pragma unroll
    for(int d=0; d<DEMB; d++) b += E[n*DEMB + d]*ubp[d*CO + tid];
    bias[tid] = b;
  }
  __syncthreads();

  int oq = (tid & 15)*4;
  int bg = tid >> 4;
  float acc[4];
  #pragma unroll
  for(int q=0;q<4;q++) acc[q] = bias[oq+q];

  const float* W = g_Wu + (size_t)n*JU + oq;
  #pragma unroll
  for(int k=0; k<3; k++){
    const float* Xk = Xs + k*1024 + bg*CO;
    const float* Wk = W + (size_t)k*128*CO;
    #pragma unroll 8
    for(int i=0; i<64; i++){
      float4 w4 = *(const float4*)(Wk + (size_t)i*CO);
      float x = Xk[i];
      acc[0] += x*w4.x; acc[1] += x*w4.y; acc[2] += x*w4.z; acc[3] += x*w4.w;
    }
  }
  *(float4*)(g_ACC2 + (size_t)n*BZ + bg*CO + oq) = make_float4(acc[0],acc[1],acc[2],acc[3]);
}

// ---------------- updB: z-half terms + tanh -> out ----------------
__global__ void __launch_bounds__(256) k_updB(float* __restrict__ out){
  __shared__ float Zs[3*1024];
  int n = blockIdx.x, tid = threadIdx.x;
  ((float4*)(Zs       ))[tid] = ((const float4*)(g_Z   + (size_t)n*BZ))[tid];
  ((float4*)(Zs + 1024))[tid] = ((const float4*)(g_ZG1 + (size_t)n*BZ))[tid];
  ((float4*)(Zs + 2048))[tid] = ((const float4*)(g_ZG2 + (size_t)n*BZ))[tid];
  __syncthreads();

  int oq = (tid & 15)*4;
  int bg = tid >> 4;
  float acc[4];
  {
    float4 a = *(const float4*)(g_ACC2 + (size_t)n*BZ + bg*CO + oq);
    acc[0]=a.x; acc[1]=a.y; acc[2]=a.z; acc[3]=a.w;
  }
  const float* W = g_Wu + (size_t)n*JU + oq;
  #pragma unroll
  for(int k=0; k<3; k++){
    const float* Zk = Zs + k*1024 + bg*CO;
    const float* Wk = W + (size_t)(k*128 + 64)*CO;
    #pragma unroll 8
    for(int i=0; i<64; i++){
      float4 w4 = *(const float4*)(Wk + (size_t)i*CO);
      float z = Zk[i];
      acc[0] += z*w4.x; acc[1] += z*w4.y; acc[2] += z*w4.z; acc[3] += z*w4.w;
    }
  }
  float4 v = make_float4(tanhf(acc[0]), tanhf(acc[1]), tanhf(acc[2]), tanhf(acc[3]));
  *(float4*)(out + ((size_t)bg*NN + n)*CO + oq) = v;
}

// ---------------- launch ----------------
extern "C" void kernel_launch(void* const* d_in, const int* in_sizes, int n_in,
                              void* d_out, int out_size){
  (void)in_sizes; (void)n_in; (void)out_size;
  const float* x   = (const float*)d_in[0];
  const float* st  = (const float*)d_in[1];
  const float* E   = (const float*)d_in[2];
  const float* gwp = (const float*)d_in[3];
  const float* gbp = (const float*)d_in[4];
  const float* uwp = (const float*)d_in[5];
  const float* ubp = (const float*)d_in[6];
  const float* lw  = (const float*)d_in[7];
  const float* lb  = (const float*)d_in[8];
  float* out = (float*)d_out;

  static cudaStream_t s1 = 0, s2 = 0;
  static cudaEvent_t evFork = 0, evW = 0, evSup = 0, evG1 = 0, evG2 = 0,
                     evGA = 0, evUA = 0;
  static int init_done = 0;
  if(!init_done){
    cudaFuncSetAttribute(mma_gemm<0,1,128>, cudaFuncAttributeMaxDynamicSharedMemorySize, SM_128);
    cudaFuncSetAttribute(mma_gemm<1,0,128>, cudaFuncAttributeMaxDynamicSharedMemorySize, SM_128);
    cudaFuncSetAttribute(mma_gemm<0,1,64>,  cudaFuncAttributeMaxDynamicSharedMemorySize, SM_64);
    cudaFuncSetAttribute(mma_gemm<1,0,64>,  cudaFuncAttributeMaxDynamicSharedMemorySize, SM_64);
    cudaStreamCreateWithFlags(&s1, cudaStreamNonBlocking);
    cudaStreamCreateWithFlags(&s2, cudaStreamNonBlocking);
    cudaEventCreateWithFlags(&evFork, cudaEventDisableTiming);
    cudaEventCreateWithFlags(&evW,    cudaEventDisableTiming);
    cudaEventCreateWithFlags(&evSup,  cudaEventDisableTiming);
    cudaEventCreateWithFlags(&evG1,   cudaEventDisableTiming);
    cudaEventCreateWithFlags(&evG2,   cudaEventDisableTiming);
    cudaEventCreateWithFlags(&evGA,   cudaEventDisableTiming);
    cudaEventCreateWithFlags(&evUA,   cudaEventDisableTiming);
    init_done = 1;
  }

  cudaEventRecord(evFork, 0);

  // s1: wcombine (only input deps) -> Wg/Wu
  cudaStreamWaitEvent(s1, evFork, 0);
  k_wcombine<<<dim3(JG/1024, NN/32), 256, 0, s1>>>(E, gwp, JG, 0);
  k_wcombine<<<dim3(JU/1024, NN/32), 256, 0, s1>>>(E, uwp, JU, 1);
  cudaEventRecord(evW, s1);

  // s2: supports || pack+cvtT
  cudaStreamWaitEvent(s2, evFork, 0);
  k_supports<<<NN, 256, 0, s2>>>(E);
  cudaEventRecord(evSup, s2);

  // main: pack + cvtT(IAS), then GEMM1 (needs supports)
  k_pack<<<(NN*BC/4)/256, 256>>>(x, st);
  k_cvtT<<<dim3(BC/32, NN/32), 256>>>(0, BC, 0);                            // IAS -> Ta
  cudaStreamWaitEvent(0, evSup, 0);
  mma_gemm<0,1,128><<<dim3(BC/128, NN/128), 256, SM_128>>>(1, 0, BC, 0, 2); // XG1; T->Tb
  cudaEventRecord(evG1, 0);

  // s2: gateA (needs XG1 + Wg) overlaps GEMM2
  cudaStreamWaitEvent(s2, evG1, 0);
  cudaStreamWaitEvent(s2, evW, 0);
  k_gateA<<<NN, 256, 0, s2>>>(E, gbp);
  cudaEventRecord(evGA, s2);

  mma_gemm<1,0,128><<<dim3(BC/128, NN/128), 256, SM_128>>>(2, 0, BC, 2, 0); // XG2
  cudaEventRecord(evG2, 0);

  // s2: updA (needs XG2 + Wu) overlaps gateB/cvtT/ZG GEMMs
  cudaStreamWaitEvent(s2, evG2, 0);
  k_updA<<<NN, 256, 0, s2>>>(E, ubp);
  cudaEventRecord(evUA, s2);

  // main: gateB (needs ACC1 via evGA; Wg ready transitively)
  cudaStreamWaitEvent(0, evGA, 0);
  k_gateB<<<NN, 256>>>(lw, lb);                                             // -> g_Z

  k_cvtT<<<dim3(BZ/32, NN/32), 256>>>(3, BZ, 0);                            // Z -> Ta
  mma_gemm<0,1,64><<<dim3(BZ/128, NN/64), 256, SM_64>>>(4, 3, BZ, 0, 2);    // ZG1; T->Tb
  mma_gemm<1,0,64><<<dim3(BZ/128, NN/64), 256, SM_64>>>(5, 3, BZ, 2, 0);    // ZG2

  cudaStreamWaitEvent(0, evUA, 0);
  k_updB<<<NN, 256>>>(out);                                                 // -> hc
}

// round 13
// speedup vs baseline: 1.0179x; 1.0179x over previous
#include <cuda_runtime.h>
#include <cuda_bf16.h>
#include <math.h>
#include <stdint.h>

#define NN    2048
#define BATCH 16
#define DEMB  10
#define CTOT  128
#define CO    64
#define BC    (BATCH*CTOT)   // 2048
#define BZ    (BATCH*CO)     // 1024
#define KC    (3*CTOT)       // 384
#define JG    (KC*CTOT)      // 49152
#define JU    (KC*CO)        // 24576

// ---------------- device scratch ----------------
__device__ float g_IAS[(size_t)NN*BC];
__device__ float g_XG1[(size_t)NN*BC];
__device__ float g_XG2[(size_t)NN*BC];
__device__ float g_Z  [(size_t)NN*BZ];
__device__ float g_ZG1[(size_t)NN*BZ];
__device__ float g_ZG2[(size_t)NN*BZ];
__device__ float g_Wg [(size_t)NN*JG];
__device__ float g_Wu [(size_t)NN*JU];
__device__ __align__(256) __nv_bfloat16 g_Shi[(size_t)NN*NN];
__device__ __align__(256) __nv_bfloat16 g_Slo[(size_t)NN*NN];
__device__ __align__(256) __nv_bfloat16 g_TaH[(size_t)NN*NN];
__device__ __align__(256) __nv_bfloat16 g_TaL[(size_t)NN*NN];
__device__ __align__(256) __nv_bfloat16 g_TbH[(size_t)NN*NN];
__device__ __align__(256) __nv_bfloat16 g_TbL[(size_t)NN*NN];

// ---------------- pickers ----------------
__device__ __forceinline__ const float* pickIn(int id){
  switch(id){ case 0: return g_IAS; case 1: return g_XG1; case 2: return g_XG2;
              case 3: return g_Z;   case 4: return g_ZG1; }
  return g_IAS;
}
__device__ __forceinline__ float* pickOut(int id){
  switch(id){ case 1: return g_XG1; case 2: return g_XG2;
              case 4: return g_ZG1; case 5: return g_ZG2; }
  return g_XG1;
}
__device__ __forceinline__ __nv_bfloat16* pickBF(int id){
  switch(id){ case 0: return g_TaH; case 1: return g_TaL;
              case 2: return g_TbH; case 3: return g_TbL; }
  return g_TaH;
}

// ---------------- warp reductions ----------------
__device__ __forceinline__ float warpMax(float v){
  #pragma unroll
  for(int o=16;o;o>>=1) v = fmaxf(v, __shfl_xor_sync(0xffffffffu, v, o));
  return v;
}
__device__ __forceinline__ float warpSum(float v){
  #pragma unroll
  for(int o=16;o;o>>=1) v += __shfl_xor_sync(0xffffffffu, v, o);
  return v;
}

// ---------------- PTX helpers ----------------
__device__ __forceinline__ uint32_t smem_u32(const void* p){
  uint32_t a;
  asm("{ .reg .u64 t; cvta.to.shared.u64 t, %1; cvt.u32.u64 %0, t; }" : "=r"(a) : "l"(p));
  return a;
}
__device__ __forceinline__ void cp16(uint32_t s, const void* g){
  asm volatile("cp.async.cg.shared.global [%0], [%1], 16;" :: "r"(s), "l"(g) : "memory");
}
__device__ __forceinline__ void cp_commit(){ asm volatile("cp.async.commit_group;" ::: "memory"); }
__device__ __forceinline__ void ldsm_x4(uint32_t* r, uint32_t a){
  asm volatile("ldmatrix.sync.aligned.m8n8.x4.shared.b16 {%0,%1,%2,%3}, [%4];"
    : "=r"(r[0]),"=r"(r[1]),"=r"(r[2]),"=r"(r[3]) : "r"(a));
}
__device__ __forceinline__ void mma16816(float* d, const uint32_t* a, const uint32_t* b){
  asm volatile("mma.sync.aligned.m16n8k16.row.col.f32.bf16.bf16.f32 "
    "{%0,%1,%2,%3}, {%4,%5,%6,%7}, {%8,%9}, {%0,%1,%2,%3};"
    : "+f"(d[0]),"+f"(d[1]),"+f"(d[2]),"+f"(d[3])
    : "r"(a[0]),"r"(a[1]),"r"(a[2]),"r"(a[3]), "r"(b[0]),"r"(b[1]));
}

// ---------------- K1: S row softmax -> bf16 hi/lo ----------------
__global__ void __launch_bounds__(256) k_supports(const float* __restrict__ E){
  __shared__ float sh[8];
  __shared__ float bcast;
  int row = blockIdx.x, tid = threadIdx.x;
  float Er[DEMB];
  #pragma unroll
  for(int d=0; d<DEMB; d++) Er[d] = E[row*DEMB + d];
  float a[8], m = -1e30f;
  #pragma unroll
  for(int q=0; q<8; q++){
    int col = tid + q*256;
    const float* Ec = E + (size_t)col*DEMB;
    float s = 0.f;
    #pragma unroll
    for(int d=0; d<DEMB; d++) s += Er[d]*Ec[d];
    s = fmaxf(s, 0.f);
    a[q] = s; m = fmaxf(m, s);
  }
  m = warpMax(m);
  if((tid&31)==0) sh[tid>>5] = m;
  __syncthreads();
  if(tid<32){ float t = (tid<8)? sh[tid] : -1e30f; t = warpMax(t); if(tid==0) bcast = t; }
  __syncthreads();
  m = bcast;
  float ssum = 0.f;
  #pragma unroll
  for(int q=0; q<8; q++){ a[q] = expf(a[q]-m); ssum += a[q]; }
  ssum = warpSum(ssum);
  __syncthreads();
  if((tid&31)==0) sh[tid>>5] = ssum;
  __syncthreads();
  if(tid<32){ float t = (tid<8)? sh[tid] : 0.f; t = warpSum(t); if(tid==0) bcast = t; }
  __syncthreads();
  float inv = 1.f/bcast;
  #pragma unroll
  for(int q=0; q<8; q++){
    float v = a[q]*inv;
    __nv_bfloat16 hi = __float2bfloat16(v);
    __nv_bfloat16 lo = __float2bfloat16(v - __bfloat162float(hi));
    size_t o = (size_t)row*NN + tid + q*256;
    g_Shi[o] = hi; g_Slo[o] = lo;
  }
}

// ---------------- K2: pack IAS ----------------
__global__ void __launch_bounds__(256) k_pack(const float* __restrict__ x,
                                              const float* __restrict__ st){
  int t = blockIdx.x*256 + threadIdx.x;
  int e = t*4;
  int n = e >> 11;
  int r = e & 2047;
  int b = r >> 7;
  int c = r & 127;
  float4 v;
  if (c < 64) v = *(const float4*)(x  + ((size_t)b*NN + n)*64 + c);
  else        v = *(const float4*)(st + ((size_t)b*NN + n)*64 + (c-64));
  *(float4*)(g_IAS + e) = v;
}

// -------- convert+transpose fp32 [2048 x W] -> bf16 hi/lo [W x 2048] --------
__global__ void __launch_bounds__(256) k_cvtT(int srcId, int W, int dstHi){
  const float* src = pickIn(srcId);
  __nv_bfloat16* dH = pickBF(dstHi);
  __nv_bfloat16* dL = pickBF(dstHi+1);
  __shared__ float t[32][33];
  int tx = threadIdx.x & 31, ty = threadIdx.x >> 5;
  int c0 = blockIdx.x*32, r0 = blockIdx.y*32;
  #pragma unroll
  for(int j=0;j<4;j++)
    t[ty+8*j][tx] = src[(size_t)(r0+ty+8*j)*W + c0+tx];
  __syncthreads();
  #pragma unroll
  for(int j=0;j<4;j++){
    float v = t[tx][ty+8*j];
    __nv_bfloat16 hi = __float2bfloat16(v);
    __nv_bfloat16 lo = __float2bfloat16(v - __bfloat162float(hi));
    size_t o = (size_t)(c0+ty+8*j)*NN + r0 + tx;
    dH[o] = hi; dL[o] = lo;
  }
}

// ---------------- K5: wcombine (float4) ----------------
__global__ void __launch_bounds__(256) k_wcombine(const float* __restrict__ E,
                                                  const float* __restrict__ wp,
                                                  int J, int which){
  float* out = which ? g_Wu : g_Wg;
  int j  = (blockIdx.x*256 + threadIdx.x)*4;
  int n0 = blockIdx.y*32;
  float4 w[DEMB];
  #pragma unroll
  for(int d=0; d<DEMB; d++) w[d] = *(const float4*)(wp + (size_t)d*J + j);
  __shared__ float Es[32*DEMB];
  for(int t=threadIdx.x; t<32*DEMB; t+=256) Es[t] = E[n0*DEMB + t];
  __syncthreads();
  #pragma unroll 2
  for(int nn=0; nn<32; nn++){
    float4 a = make_float4(0.f,0.f,0.f,0.f);
    #pragma unroll
    for(int d=0; d<DEMB; d++){
      float e = Es[nn*DEMB+d];
      a.x += e*w[d].x; a.y += e*w[d].y; a.z += e*w[d].z; a.w += e*w[d].w;
    }
    *(float4*)(out + (size_t)(n0+nn)*J + j) = a;
  }
}

// ---------------- HMMA bf16x3 GEMM (R6 config + fragment pipelining) --------
#define PITCH    48

template<int MODE, int WRITE_T, int TM>
__global__ void __launch_bounds__(256,2) mma_gemm(int cId, int dId, int Ncols,
                                                  int bHiId, int tHiId){
  constexpr int WM   = (TM == 128) ? 4 : 2;
  constexpr int WN   = 8 / WM;
  constexpr int NT   = (128 / WN) / 8;
  constexpr int NTP  = NT / 2;
  constexpr int A_T  = TM * PITCH;
  constexpr int B_T  = 128 * PITCH;
  constexpr int STG  = 2*A_T + 2*B_T;
  constexpr int NTRANS = (2*TM + 2*128) * 2;

  extern __shared__ char smem[];
  float*       C = pickOut(cId);
  const float* D = pickIn(dId);
  const __nv_bfloat16* Bh = pickBF(bHiId);
  const __nv_bfloat16* Bl = pickBF(bHiId+1);
  const uint32_t sb = smem_u32(smem);
  const int tid = threadIdx.x, wid = tid >> 5, lane = tid & 31;
  const int warpM = wid % WM, warpN = wid / WM;
  const size_t row0 = (size_t)blockIdx.y * TM;
  const size_t n0   = (size_t)blockIdx.x * 128;

  float acc[2][NT][4];
  #pragma unroll
  for(int m=0;m<2;m++)
    #pragma unroll
    for(int n=0;n<NT;n++)
      #pragma unroll
      for(int q=0;q<4;q++) acc[m][n][q] = 0.f;

  auto issue = [&](int c){
    const size_t kb = (size_t)c * 16;
    const uint32_t bo = sb + (uint32_t)(c & 3) * STG;
    #pragma unroll
    for(int u = 0; u < NTRANS/256; u++){
      int e  = tid + u*256;
      int h  = e & 1;
      int rr = e >> 1;
      if(rr < TM){
        cp16(bo + rr*PITCH + h*16, g_Shi + (row0 + rr)*(size_t)NN + kb + h*8);
      } else if(rr < 2*TM){
        int r = rr - TM;
        cp16(bo + A_T + r*PITCH + h*16, g_Slo + (row0 + r)*(size_t)NN + kb + h*8);
      } else if(rr < 2*TM + 128){
        int r = rr - 2*TM;
        cp16(bo + 2*A_T + r*PITCH + h*16, Bh + (n0 + r)*(size_t)NN + kb + h*8);
      } else {
        int r = rr - 2*TM - 128;
        cp16(bo + 2*A_T + B_T + r*PITCH + h*16, Bl + (n0 + r)*(size_t)NN + kb + h*8);
      }
    }
    cp_commit();
  };

  issue(0); issue(1); issue(2);

  const uint32_t aoff = (uint32_t)((warpM*32 + (lane & 15))*PITCH + (lane >> 4)*16);
  const uint32_t boff = (uint32_t)(2*A_T + (warpN*(NT*8) + ((lane >> 4) & 1)*8 + (lane & 7))*PITCH
                                   + ((lane >> 3) & 1)*16);

  for(int c=0; c<128; c++){
    if(c <= 125)      asm volatile("cp.async.wait_group 2;" ::: "memory");
    else if(c == 126) asm volatile("cp.async.wait_group 1;" ::: "memory");
    else              asm volatile("cp.async.wait_group 0;" ::: "memory");
    __syncthreads();
    if(c + 3 < 128) issue(c+3);

    const uint32_t bo = sb + (uint32_t)(c & 3) * STG;
    uint32_t afH[2][4], afL[2][4];
    #pragma unroll
    for(int mt=0; mt<2; mt++){
      uint32_t ad = bo + aoff + (uint32_t)(mt*16*PITCH);
      ldsm_x4(afH[mt], ad);
      ldsm_x4(afL[mt], ad + A_T);
    }
    // ---- software-pipelined B fragments: double buffer across ntp ----
    uint32_t bf[2][2][4];                 // [buf][H/L][4]
    {
      uint32_t bd0 = bo + boff;
      ldsm_x4(bf[0][0], bd0);
      ldsm_x4(bf[0][1], bd0 + B_T);
    }
    #pragma unroll
    for(int ntp=0; ntp<NTP; ntp++){
      const int cur = ntp & 1, nxt = cur ^ 1;
      if(ntp + 1 < NTP){
        uint32_t bd = bo + boff + (uint32_t)((ntp+1)*16*PITCH);
        ldsm_x4(bf[nxt][0], bd);
        ldsm_x4(bf[nxt][1], bd + B_T);
      }
      const uint32_t* bH = bf[cur][0];
      const uint32_t* bL = bf[cur][1];
      mma16816(acc[0][2*ntp],   afH[0], bH);
      mma16816(acc[1][2*ntp],   afH[1], bH);
      mma16816(acc[0][2*ntp+1], afH[0], bH+2);
      mma16816(acc[1][2*ntp+1], afH[1], bH+2);
      mma16816(acc[0][2*ntp],   afH[0], bL);
      mma16816(acc[1][2*ntp],   afH[1], bL);
      mma16816(acc[0][2*ntp+1], afH[0], bL+2);
      mma16816(acc[1][2*ntp+1], afH[1], bL+2);
      mma16816(acc[0][2*ntp],   afL[0], bH);
      mma16816(acc[1][2*ntp],   afL[1], bH);
      mma16816(acc[0][2*ntp+1], afL[0], bH+2);
      mma16816(acc[1][2*ntp+1], afL[1], bH+2);
    }
  }

  // ---------------- epilogue ----------------
  const int g = lane >> 2, tg = lane & 3;
  #pragma unroll
  for(int mt=0; mt<2; mt++){
    size_t r0g = row0 + warpM*32 + mt*16 + g;
    #pragma unroll
    for(int nt=0; nt<NT; nt++){
      size_t col = n0 + warpN*(NT*8) + nt*8 + tg*2;
      size_t o0 = r0g      *(size_t)Ncols + col;
      size_t o1 = (r0g + 8)*(size_t)Ncols + col;
      float2 v0 = make_float2(acc[mt][nt][0], acc[mt][nt][1]);
      float2 v1 = make_float2(acc[mt][nt][2], acc[mt][nt][3]);
      if(MODE == 1){
        float2 d0 = *(const float2*)(D + o0);
        float2 d1 = *(const float2*)(D + o1);
        v0.x = 2.f*v0.x - d0.x; v0.y = 2.f*v0.y - d0.y;
        v1.x = 2.f*v1.x - d1.x; v1.y = 2.f*v1.y - d1.y;
      }
      *(float2*)(C + o0) = v0;
      *(float2*)(C + o1) = v1;
    }
  }

  if(WRITE_T){
    __nv_bfloat16* TH = pickBF(tHiId);
    __nv_bfloat16* TL = pickBF(tHiId+1);
    float* tile = (float*)smem;          // [TM][132]
    __syncthreads();
    #pragma unroll
    for(int mt=0; mt<2; mt++){
      int rr = warpM*32 + mt*16 + g;
      #pragma unroll
      for(int nt=0; nt<NT; nt++){
        int cc = warpN*(NT*8) + nt*8 + tg*2;
        tile[rr*132 + cc]         = acc[mt][nt][0];
        tile[rr*132 + cc + 1]     = acc[mt][nt][1];
        tile[(rr+8)*132 + cc]     = acc[mt][nt][2];
        tile[(rr+8)*132 + cc + 1] = acc[mt][nt][3];
      }
    }
    __syncthreads();
    int c0 = tid >> 1, half = tid & 1;
    size_t baseO = (size_t)(n0 + c0)*NN + row0 + half*(TM/2);
    #pragma unroll
    for(int ch=0; ch<TM/16; ch++){
      __nv_bfloat16 hb[8], lb8[8];
      #pragma unroll
      for(int e=0; e<8; e++){
        float v = tile[(half*(TM/2) + ch*8 + e)*132 + c0];
        __nv_bfloat16 hi = __float2bfloat16(v);
        hb[e] = hi;
        lb8[e] = __float2bfloat16(v - __bfloat162float(hi));
      }
      *(uint4*)(TH + baseO + ch*8) = *(uint4*)hb;
      *(uint4*)(TL + baseO + ch*8) = *(uint4*)lb8;
    }
  }
}

#define SM_128  (4*(2*(128*PITCH) + 2*(128*PITCH)))   // 98304
#define SM_64   (4*(2*(64*PITCH)  + 2*(128*PITCH)))   // 73728

// ---------------- K6: gate final ----------------
__global__ void __launch_bounds__(256) k_gate_final(const float* __restrict__ E,
                                                    const float* __restrict__ gbp,
                                                    const float* __restrict__ lw,
                                                    const float* __restrict__ lb){
  __shared__ float smA[128*68];
  __shared__ float ysig[BATCH*CTOT];
  __shared__ float bias[CTOT];
  int n = blockIdx.x, tid = threadIdx.x;

  float* Xs = smA;
  for(int t=tid; t<512; t+=256){
    ((float4*)Xs)[t]        = ((const float4*)(g_IAS + (size_t)n*BC))[t];
    ((float4*)(Xs+2048))[t] = ((const float4*)(g_XG1 + (size_t)n*BC))[t];
    ((float4*)(Xs+4096))[t] = ((const float4*)(g_XG2 + (size_t)n*BC))[t];
  }
  if(tid < CTOT){
    float b = 0.f;
    #pragma unroll
    for(int d=0; d<DEMB; d++) b += E[n*DEMB + d]*gbp[d*CTOT + tid];
    bias[tid] = b;
  }
  __syncthreads();

  int oq = (tid & 31)*4;
  int b0 = (tid >> 5)*2, b1 = b0 + 1;
  float acc[2][4];
  #pragma unroll
  for(int q=0;q<4;q++){ acc[0][q] = bias[oq+q]; acc[1][q] = bias[oq+q]; }

  const float* W = g_Wg + (size_t)n*JG + oq;
  #pragma unroll
  for(int k=0; k<3; k++){
    const float* Xk0 = Xs + k*2048 + b0*CTOT;
    const float* Xk1 = Xs + k*2048 + b1*CTOT;
    const float* Wk  = W + (size_t)k*128*CTOT;
    #pragma unroll 8
    for(int i=0; i<128; i++){
      float4 w4 = *(const float4*)(Wk + (size_t)i*CTOT);
      float x0 = Xk0[i], x1 = Xk1[i];
      acc[0][0] += x0*w4.x; acc[0][1] += x0*w4.y; acc[0][2] += x0*w4.z; acc[0][3] += x0*w4.w;
      acc[1][0] += x1*w4.x; acc[1][1] += x1*w4.y; acc[1][2] += x1*w4.z; acc[1][3] += x1*w4.w;
    }
  }
  #pragma unroll
  for(int bb=0; bb<2; bb++){
    float4 v;
    v.x = 1.f/(1.f + expf(-acc[bb][0]));
    v.y = 1.f/(1.f + expf(-acc[bb][1]));
    v.z = 1.f/(1.f + expf(-acc[bb][2]));
    v.w = 1.f/(1.f + expf(-acc[bb][3]));
    *(float4*)(ysig + (b0+bb)*CTOT + oq) = v;
  }
  __syncthreads();

  float* lwT = smA;
  for(int t=tid; t<CO*CTOT; t+=256){ int c = t>>7, oo = t&127; lwT[oo*68 + c] = lw[t]; }
  __syncthreads();

  int c4  = (tid & 15)*4;
  int bg  = tid >> 4;
  float acc2[4];
  #pragma unroll
  for(int q=0;q<4;q++) acc2[q] = lb[c4+q];
  const float* Ys = ysig + bg*CTOT;
  #pragma unroll 8
  for(int o2=0; o2<CTOT; o2++){
    float4 w4 = *(const float4*)(lwT + o2*68 + c4);
    float y = Ys[o2];
    acc2[0] += y*w4.x; acc2[1] += y*w4.y; acc2[2] += y*w4.z; acc2[3] += y*w4.w;
  }
  *(float4*)(g_Z + (size_t)n*BZ + bg*CO + c4) = make_float4(acc2[0],acc2[1],acc2[2],acc2[3]);
}

// ---------------- K9: upd final ----------------
__global__ void __launch_bounds__(256) k_upd_final(const float* __restrict__ E,
                                                   const float* __restrict__ ubp,
                                                   float* __restrict__ out){
  __shared__ float Xs[3*1024];
  __shared__ float Zs[3*1024];
  __shared__ float bias[CO];
  int n = blockIdx.x, tid = threadIdx.x;
  {
    const float* s0 = g_IAS + (size_t)n*BC;
    const float* s1 = g_XG1 + (size_t)n*BC;
    const float* s2 = g_XG2 + (size_t)n*BC;
    int b = tid >> 4, f = (tid & 15)*4;
    ((float4*)(Xs       ))[tid] = *(const float4*)(s0 + b*CTOT + f);
    ((float4*)(Xs + 1024))[tid] = *(const float4*)(s1 + b*CTOT + f);
    ((float4*)(Xs + 2048))[tid] = *(const float4*)(s2 + b*CTOT + f);
    ((float4*)(Zs       ))[tid] = ((const float4*)(g_Z   + (size_t)n*BZ))[tid];
    ((float4*)(Zs + 1024))[tid] = ((const float4*)(g_ZG1 + (size_t)n*BZ))[tid];
    ((float4*)(Zs + 2048))[tid] = ((const float4*)(g_ZG2 + (size_t)n*BZ))[tid];
  }
  if(tid < CO){
    float b = 0.f;
    #pragma unroll
    for(int d=0; d<DEMB; d++) b += E[n*DEMB + d]*ubp[d*CO + tid];
    bias[tid] = b;
  }
  __syncthreads();

  int oq = (tid & 15)*4;
  int bg = tid >> 4;
  float acc[4];
  #pragma unroll
  for(int q=0;q<4;q++) acc[q] = bias[oq+q];

  const float* W = g_Wu + (size_t)n*JU + oq;
  #pragma unroll
  for(int k=0; k<3; k++){
    const float* Xk = Xs + k*1024 + bg*CO;
    const float* Zk = Zs + k*1024 + bg*CO;
    const float* Wk = W + (size_t)k*128*CO;
    #pragma unroll 8
    for(int i=0; i<64; i++){
      float4 w4 = *(const float4*)(Wk + (size_t)i*CO);
      float x = Xk[i];
      acc[0] += x*w4.x; acc[1] += x*w4.y; acc[2] += x*w4.z; acc[3] += x*w4.w;
    }
    const float* Wk2 = Wk + (size_t)64*CO;
    #pragma unroll 8
    for(int i=0; i<64; i++){
      float4 w4 = *(const float4*)(Wk2 + (size_t)i*CO);
      float z = Zk[i];
      acc[0] += z*w4.x; acc[1] += z*w4.y; acc[2] += z*w4.z; acc[3] += z*w4.w;
    }
  }
  float4 v = make_float4(tanhf(acc[0]), tanhf(acc[1]), tanhf(acc[2]), tanhf(acc[3]));
  *(float4*)(out + ((size_t)bg*NN + n)*CO + oq) = v;
}

// ---------------- launch ----------------
extern "C" void kernel_launch(void* const* d_in, const int* in_sizes, int n_in,
                              void* d_out, int out_size){
  (void)in_sizes; (void)n_in; (void)out_size;
  const float* x   = (const float*)d_in[0];
  const float* st  = (const float*)d_in[1];
  const float* E   = (const float*)d_in[2];
  const float* gwp = (const float*)d_in[3];
  const float* gbp = (const float*)d_in[4];
  const float* uwp = (const float*)d_in[5];
  const float* ubp = (const float*)d_in[6];
  const float* lw  = (const float*)d_in[7];
  const float* lb  = (const float*)d_in[8];
  float* out = (float*)d_out;

  static cudaStream_t sSide = 0;
  static cudaEvent_t evFork = 0, evJoin = 0;
  static int init_done = 0;
  if(!init_done){
    cudaFuncSetAttribute(mma_gemm<0,1,128>, cudaFuncAttributeMaxDynamicSharedMemorySize, SM_128);
    cudaFuncSetAttribute(mma_gemm<1,0,128>, cudaFuncAttributeMaxDynamicSharedMemorySize, SM_128);
    cudaFuncSetAttribute(mma_gemm<0,1,64>,  cudaFuncAttributeMaxDynamicSharedMemorySize, SM_64);
    cudaFuncSetAttribute(mma_gemm<1,0,64>,  cudaFuncAttributeMaxDynamicSharedMemorySize, SM_64);
    cudaStreamCreateWithFlags(&sSide, cudaStreamNonBlocking);
    cudaEventCreateWithFlags(&evFork, cudaEventDisableTiming);
    cudaEventCreateWithFlags(&evJoin, cudaEventDisableTiming);
    init_done = 1;
  }

  k_supports<<<NN, 256>>>(E);
  k_pack<<<(NN*BC/4)/256, 256>>>(x, st);
  k_cvtT<<<dim3(BC/32, NN/32), 256>>>(0, BC, 0);                            // IAS -> Ta

  // launch 4 (profiled): big GEMM1
  mma_gemm<0,1,128><<<dim3(BC/128, NN/128), 256, SM_128>>>(1, 0, BC, 0, 2); // XG1; T->Tb

  cudaEventRecord(evFork, 0);
  cudaStreamWaitEvent(sSide, evFork, 0);
  k_wcombine<<<dim3(JG/1024, NN/32), 256, 0, sSide>>>(E, gwp, JG, 0);
  k_wcombine<<<dim3(JU/1024, NN/32), 256, 0, sSide>>>(E, uwp, JU, 1);
  cudaEventRecord(evJoin, sSide);

  mma_gemm<1,0,128><<<dim3(BC/128, NN/128), 256, SM_128>>>(2, 0, BC, 2, 0); // XG2

  cudaStreamWaitEvent(0, evJoin, 0);
  k_gate_final<<<NN, 256>>>(E, gbp, lw, lb);                                // -> g_Z

  k_cvtT<<<dim3(BZ/32, NN/32), 256>>>(3, BZ, 0);                            // Z -> Ta
  mma_gemm<0,1,64><<<dim3(BZ/128, NN/64), 256, SM_64>>>(4, 3, BZ, 0, 2);    // ZG1; T->Tb
  mma_gemm<1,0,64><<<dim3(BZ/128, NN/64), 256, SM_64>>>(5, 3, BZ, 2, 0);    // ZG2

  k_upd_final<<<NN, 256>>>(E, ubp, out);                                    // -> hc
}

// round 14
// speedup vs baseline: 1.2117x; 1.1904x over previous
#include <cuda_runtime.h>
#include <cuda_fp16.h>
#include <math.h>
#include <stdint.h>

#define NN    2048
#define BATCH 16
#define DEMB  10
#define CTOT  128
#define CO    64
#define BC    (BATCH*CTOT)   // 2048
#define BZ    (BATCH*CO)     // 1024
#define KC    (3*CTOT)       // 384
#define JG    (KC*CTOT)      // 49152
#define JU    (KC*CO)        // 24576

// ---------------- device scratch ----------------
__device__ float g_IAS[(size_t)NN*BC];
__device__ float g_XG1[(size_t)NN*BC];
__device__ float g_XG2[(size_t)NN*BC];
__device__ float g_Z  [(size_t)NN*BZ];
__device__ float g_ZG1[(size_t)NN*BZ];
__device__ float g_ZG2[(size_t)NN*BZ];
__device__ float g_Wg [(size_t)NN*JG];
__device__ float g_Wu [(size_t)NN*JU];
__device__ __align__(256) __half g_Sh [(size_t)NN*NN];
__device__ __align__(256) __half g_TaH[(size_t)NN*NN];
__device__ __align__(256) __half g_TaL[(size_t)NN*NN];
__device__ __align__(256) __half g_TbH[(size_t)NN*NN];
__device__ __align__(256) __half g_TbL[(size_t)NN*NN];

// ---------------- pickers ----------------
__device__ __forceinline__ const float* pickIn(int id){
  switch(id){ case 0: return g_IAS; case 1: return g_XG1; case 2: return g_XG2;
              case 3: return g_Z;   case 4: return g_ZG1; }
  return g_IAS;
}
__device__ __forceinline__ float* pickOut(int id){
  switch(id){ case 1: return g_XG1; case 2: return g_XG2;
              case 4: return g_ZG1; case 5: return g_ZG2; }
  return g_XG1;
}
__device__ __forceinline__ __half* pickHF(int id){
  switch(id){ case 0: return g_TaH; case 1: return g_TaL;
              case 2: return g_TbH; case 3: return g_TbL; }
  return g_TaH;
}

// ---------------- warp reductions ----------------
__device__ __forceinline__ float warpMax(float v){
  #pragma unroll
  for(int o=16;o;o>>=1) v = fmaxf(v, __shfl_xor_sync(0xffffffffu, v, o));
  return v;
}
__device__ __forceinline__ float warpSum(float v){
  #pragma unroll
  for(int o=16;o;o>>=1) v += __shfl_xor_sync(0xffffffffu, v, o);
  return v;
}

// ---------------- PTX helpers ----------------
__device__ __forceinline__ uint32_t smem_u32(const void* p){
  uint32_t a;
  asm("{ .reg .u64 t; cvta.to.shared.u64 t, %1; cvt.u32.u64 %0, t; }" : "=r"(a) : "l"(p));
  return a;
}
__device__ __forceinline__ void cp16(uint32_t s, const void* g){
  asm volatile("cp.async.cg.shared.global [%0], [%1], 16;" :: "r"(s), "l"(g) : "memory");
}
__device__ __forceinline__ void cp_commit(){ asm volatile("cp.async.commit_group;" ::: "memory"); }
__device__ __forceinline__ void ldsm_x4(uint32_t* r, uint32_t a){
  asm volatile("ldmatrix.sync.aligned.m8n8.x4.shared.b16 {%0,%1,%2,%3}, [%4];"
    : "=r"(r[0]),"=r"(r[1]),"=r"(r[2]),"=r"(r[3]) : "r"(a));
}
__device__ __forceinline__ void mma16816(float* d, const uint32_t* a, const uint32_t* b){
  asm volatile("mma.sync.aligned.m16n8k16.row.col.f32.f16.f16.f32 "
    "{%0,%1,%2,%3}, {%4,%5,%6,%7}, {%8,%9}, {%0,%1,%2,%3};"
    : "+f"(d[0]),"+f"(d[1]),"+f"(d[2]),"+f"(d[3])
    : "r"(a[0]),"r"(a[1]),"r"(a[2]),"r"(a[3]), "r"(b[0]),"r"(b[1]));
}

// ---------------- K1: S row softmax -> fp16 ----------------
__global__ void __launch_bounds__(256) k_supports(const float* __restrict__ E){
  __shared__ float sh[8];
  __shared__ float bcast;
  int row = blockIdx.x, tid = threadIdx.x;
  float Er[DEMB];
  #pragma unroll
  for(int d=0; d<DEMB; d++) Er[d] = E[row*DEMB + d];
  float a[8], m = -1e30f;
  #pragma unroll
  for(int q=0; q<8; q++){
    int col = tid + q*256;
    const float* Ec = E + (size_t)col*DEMB;
    float s = 0.f;
    #pragma unroll
    for(int d=0; d<DEMB; d++) s += Er[d]*Ec[d];
    s = fmaxf(s, 0.f);
    a[q] = s; m = fmaxf(m, s);
  }
  m = warpMax(m);
  if((tid&31)==0) sh[tid>>5] = m;
  __syncthreads();
  if(tid<32){ float t = (tid<8)? sh[tid] : -1e30f; t = warpMax(t); if(tid==0) bcast = t; }
  __syncthreads();
  m = bcast;
  float ssum = 0.f;
  #pragma unroll
  for(int q=0; q<8; q++){ a[q] = expf(a[q]-m); ssum += a[q]; }
  ssum = warpSum(ssum);
  __syncthreads();
  if((tid&31)==0) sh[tid>>5] = ssum;
  __syncthreads();
  if(tid<32){ float t = (tid<8)? sh[tid] : 0.f; t = warpSum(t); if(tid==0) bcast = t; }
  __syncthreads();
  float inv = 1.f/bcast;
  #pragma unroll
  for(int q=0; q<8; q++)
    g_Sh[(size_t)row*NN + tid + q*256] = __float2half_rn(a[q]*inv);
}

// ---------------- K2: pack IAS ----------------
__global__ void __launch_bounds__(256) k_pack(const float* __restrict__ x,
                                              const float* __restrict__ st){
  int t = blockIdx.x*256 + threadIdx.x;
  int e = t*4;
  int n = e >> 11;
  int r = e & 2047;
  int b = r >> 7;
  int c = r & 127;
  float4 v;
  if (c < 64) v = *(const float4*)(x  + ((size_t)b*NN + n)*64 + c);
  else        v = *(const float4*)(st + ((size_t)b*NN + n)*64 + (c-64));
  *(float4*)(g_IAS + e) = v;
}

// -------- convert+transpose fp32 [2048 x W] -> fp16 hi/lo [W x 2048] --------
__global__ void __launch_bounds__(256) k_cvtT(int srcId, int W, int dstHi){
  const float* src = pickIn(srcId);
  __half* dH = pickHF(dstHi);
  __half* dL = pickHF(dstHi+1);
  __shared__ float t[32][33];
  int tx = threadIdx.x & 31, ty = threadIdx.x >> 5;
  int c0 = blockIdx.x*32, r0 = blockIdx.y*32;
  #pragma unroll
  for(int j=0;j<4;j++)
    t[ty+8*j][tx] = src[(size_t)(r0+ty+8*j)*W + c0+tx];
  __syncthreads();
  #pragma unroll
  for(int j=0;j<4;j++){
    float v = t[tx][ty+8*j];
    __half hi = __float2half_rn(v);
    __half lo = __float2half_rn(v - __half2float(hi));
    size_t o = (size_t)(c0+ty+8*j)*NN + r0 + tx;
    dH[o] = hi; dL[o] = lo;
  }
}

// ---------------- K5: wcombine (float4) ----------------
__global__ void __launch_bounds__(256) k_wcombine(const float* __restrict__ E,
                                                  const float* __restrict__ wp,
                                                  int J, int which){
  float* out = which ? g_Wu : g_Wg;
  int j  = (blockIdx.x*256 + threadIdx.x)*4;
  int n0 = blockIdx.y*32;
  float4 w[DEMB];
  #pragma unroll
  for(int d=0; d<DEMB; d++) w[d] = *(const float4*)(wp + (size_t)d*J + j);
  __shared__ float Es[32*DEMB];
  for(int t=threadIdx.x; t<32*DEMB; t+=256) Es[t] = E[n0*DEMB + t];
  __syncthreads();
  #pragma unroll 2
  for(int nn=0; nn<32; nn++){
    float4 a = make_float4(0.f,0.f,0.f,0.f);
    #pragma unroll
    for(int d=0; d<DEMB; d++){
      float e = Es[nn*DEMB+d];
      a.x += e*w[d].x; a.y += e*w[d].y; a.z += e*w[d].z; a.w += e*w[d].w;
    }
    *(float4*)(out + (size_t)(n0+nn)*J + j) = a;
  }
}

// ---------------- HMMA fp16x2 GEMM: C = S@B (MODE0) / 2*S@B - D (MODE1) -----
// A = S (fp16, single), B = Bh + Bl (fp16 split). 2 products: AhBh + AhBl.
// Tiles per stage: A (TM x16), Bh (128x16), Bl (128x16). K-chunk 16, 4 stages.
#define PITCH    48

template<int MODE, int WRITE_T, int TM>
__global__ void __launch_bounds__(256,2) mma_gemm(int cId, int dId, int Ncols,
                                                  int bHiId, int tHiId){
  constexpr int WM   = (TM == 128) ? 4 : 2;
  constexpr int WN   = 8 / WM;
  constexpr int NT   = (128 / WN) / 8;
  constexpr int NTP  = NT / 2;
  constexpr int A_T  = TM * PITCH;
  constexpr int B_T  = 128 * PITCH;
  constexpr int STG  = A_T + 2*B_T;
  constexpr int NTRANS = (TM + 2*128) * 2;
  constexpr int NU   = (NTRANS + 255) / 256;

  extern __shared__ char smem[];
  float*       C = pickOut(cId);
  const float* D = pickIn(dId);
  const __half* Bh = pickHF(bHiId);
  const __half* Bl = pickHF(bHiId+1);
  const uint32_t sb = smem_u32(smem);
  const int tid = threadIdx.x, wid = tid >> 5, lane = tid & 31;
  const int warpM = wid % WM, warpN = wid / WM;
  const size_t row0 = (size_t)blockIdx.y * TM;
  const size_t n0   = (size_t)blockIdx.x * 128;

  float acc[2][NT][4];
  #pragma unroll
  for(int m=0;m<2;m++)
    #pragma unroll
    for(int n=0;n<NT;n++)
      #pragma unroll
      for(int q=0;q<4;q++) acc[m][n][q] = 0.f;

  auto issue = [&](int c){
    const size_t kb = (size_t)c * 16;
    const uint32_t bo = sb + (uint32_t)(c & 3) * STG;
    #pragma unroll
    for(int u = 0; u < NU; u++){
      int e  = tid + u*256;
      if(NTRANS % 256 != 0 && e >= NTRANS) break;
      int h  = e & 1;
      int rr = e >> 1;
      if(rr < TM){
        cp16(bo + rr*PITCH + h*16, g_Sh + (row0 + rr)*(size_t)NN + kb + h*8);
      } else if(rr < TM + 128){
        int r = rr - TM;
        cp16(bo + A_T + r*PITCH + h*16, Bh + (n0 + r)*(size_t)NN + kb + h*8);
      } else {
        int r = rr - TM - 128;
        cp16(bo + A_T + B_T + r*PITCH + h*16, Bl + (n0 + r)*(size_t)NN + kb + h*8);
      }
    }
    cp_commit();
  };

  issue(0); issue(1); issue(2);

  const uint32_t aoff = (uint32_t)((warpM*32 + (lane & 15))*PITCH + (lane >> 4)*16);
  const uint32_t boff = (uint32_t)(A_T + (warpN*(NT*8) + ((lane >> 4) & 1)*8 + (lane & 7))*PITCH
                                   + ((lane >> 3) & 1)*16);

  for(int c=0; c<128; c++){
    if(c <= 125)      asm volatile("cp.async.wait_group 2;" ::: "memory");
    else if(c == 126) asm volatile("cp.async.wait_group 1;" ::: "memory");
    else              asm volatile("cp.async.wait_group 0;" ::: "memory");
    __syncthreads();
    if(c + 3 < 128) issue(c+3);

    const uint32_t bo = sb + (uint32_t)(c & 3) * STG;
    uint32_t af[2][4];
    #pragma unroll
    for(int mt=0; mt<2; mt++)
      ldsm_x4(af[mt], bo + aoff + (uint32_t)(mt*16*PITCH));
    #pragma unroll
    for(int ntp=0; ntp<NTP; ntp++){
      uint32_t bd = bo + boff + (uint32_t)(ntp*16*PITCH);
      uint32_t bH[4], bL[4];
      ldsm_x4(bH, bd);
      ldsm_x4(bL, bd + B_T);
      mma16816(acc[0][2*ntp],   af[0], bH);
      mma16816(acc[1][2*ntp],   af[1], bH);
      mma16816(acc[0][2*ntp+1], af[0], bH+2);
      mma16816(acc[1][2*ntp+1], af[1], bH+2);
      mma16816(acc[0][2*ntp],   af[0], bL);
      mma16816(acc[1][2*ntp],   af[1], bL);
      mma16816(acc[0][2*ntp+1], af[0], bL+2);
      mma16816(acc[1][2*ntp+1], af[1], bL+2);
    }
  }

  // ---------------- epilogue ----------------
  const int g = lane >> 2, tg = lane & 3;
  #pragma unroll
  for(int mt=0; mt<2; mt++){
    size_t r0g = row0 + warpM*32 + mt*16 + g;
    #pragma unroll
    for(int nt=0; nt<NT; nt++){
      size_t col = n0 + warpN*(NT*8) + nt*8 + tg*2;
      size_t o0 = r0g      *(size_t)Ncols + col;
      size_t o1 = (r0g + 8)*(size_t)Ncols + col;
      float2 v0 = make_float2(acc[mt][nt][0], acc[mt][nt][1]);
      float2 v1 = make_float2(acc[mt][nt][2], acc[mt][nt][3]);
      if(MODE == 1){
        float2 d0 = *(const float2*)(D + o0);
        float2 d1 = *(const float2*)(D + o1);
        v0.x = 2.f*v0.x - d0.x; v0.y = 2.f*v0.y - d0.y;
        v1.x = 2.f*v1.x - d1.x; v1.y = 2.f*v1.y - d1.y;
      }
      *(float2*)(C + o0) = v0;
      *(float2*)(C + o1) = v1;
    }
  }

  if(WRITE_T){
    __half* TH = pickHF(tHiId);
    __half* TL = pickHF(tHiId+1);
    float* tile = (float*)smem;          // [TM][132]
    __syncthreads();
    #pragma unroll
    for(int mt=0; mt<2; mt++){
      int rr = warpM*32 + mt*16 + g;
      #pragma unroll
      for(int nt=0; nt<NT; nt++){
        int cc = warpN*(NT*8) + nt*8 + tg*2;
        tile[rr*132 + cc]         = acc[mt][nt][0];
        tile[rr*132 + cc + 1]     = acc[mt][nt][1];
        tile[(rr+8)*132 + cc]     = acc[mt][nt][2];
        tile[(rr+8)*132 + cc + 1] = acc[mt][nt][3];
      }
    }
    __syncthreads();
    int c0 = tid >> 1, half_ = tid & 1;
    size_t baseO = (size_t)(n0 + c0)*NN + row0 + half_*(TM/2);
    #pragma unroll
    for(int ch=0; ch<TM/16; ch++){
      __half hb[8], lb8[8];
      #pragma unroll
      for(int e=0; e<8; e++){
        float v = tile[(half_*(TM/2) + ch*8 + e)*132 + c0];
        __half hi = __float2half_rn(v);
        hb[e] = hi;
        lb8[e] = __float2half_rn(v - __half2float(hi));
      }
      *(uint4*)(TH + baseO + ch*8) = *(uint4*)hb;
      *(uint4*)(TL + baseO + ch*8) = *(uint4*)lb8;
    }
  }
}

#define SM_128  (4*((128*PITCH) + 2*(128*PITCH)))   // 73728
#define SM_64   (4*((64*PITCH)  + 2*(128*PITCH)))   // 61440

// ---------------- K6: gate final ----------------
__global__ void __launch_bounds__(256) k_gate_final(const float* __restrict__ E,
                                                    const float* __restrict__ gbp,
                                                    const float* __restrict__ lw,
                                                    const float* __restrict__ lb){
  __shared__ float smA[128*68];
  __shared__ float ysig[BATCH*CTOT];
  __shared__ float bias[CTOT];
  int n = blockIdx.x, tid = threadIdx.x;

  float* Xs = smA;
  for(int t=tid; t<512; t+=256){
    ((float4*)Xs)[t]        = ((const float4*)(g_IAS + (size_t)n*BC))[t];
    ((float4*)(Xs+2048))[t] = ((const float4*)(g_XG1 + (size_t)n*BC))[t];
    ((float4*)(Xs+4096))[t] = ((const float4*)(g_XG2 + (size_t)n*BC))[t];
  }
  if(tid < CTOT){
    float b = 0.f;
    #pragma unroll
    for(int d=0; d<DEMB; d++) b += E[n*DEMB + d]*gbp[d*CTOT + tid];
    bias[tid] = b;
  }
  __syncthreads();

  int oq = (tid & 31)*4;
  int b0 = (tid >> 5)*2, b1 = b0 + 1;
  float acc[2][4];
  #pragma unroll
  for(int q=0;q<4;q++){ acc[0][q] = bias[oq+q]; acc[1][q] = bias[oq+q]; }

  const float* W = g_Wg + (size_t)n*JG + oq;
  #pragma unroll
  for(int k=0; k<3; k++){
    const float* Xk0 = Xs + k*2048 + b0*CTOT;
    const float* Xk1 = Xs + k*2048 + b1*CTOT;
    const float* Wk  = W + (size_t)k*128*CTOT;
    #pragma unroll 8
    for(int i=0; i<128; i++){
      float4 w4 = *(const float4*)(Wk + (size_t)i*CTOT);
      float x0 = Xk0[i], x1 = Xk1[i];
      acc[0][0] += x0*w4.x; acc[0][1] += x0*w4.y; acc[0][2] += x0*w4.z; acc[0][3] += x0*w4.w;
      acc[1][0] += x1*w4.x; acc[1][1] += x1*w4.y; acc[1][2] += x1*w4.z; acc[1][3] += x1*w4.w;
    }
  }
  #pragma unroll
  for(int bb=0; bb<2; bb++){
    float4 v;
    v.x = 1.f/(1.f + expf(-acc[bb][0]));
    v.y = 1.f/(1.f + expf(-acc[bb][1]));
    v.z = 1.f/(1.f + expf(-acc[bb][2]));
    v.w = 1.f/(1.f + expf(-acc[bb][3]));
    *(float4*)(ysig + (b0+bb)*CTOT + oq) = v;
  }
  __syncthreads();

  float* lwT = smA;
  for(int t=tid; t<CO*CTOT; t+=256){ int c = t>>7, oo = t&127; lwT[oo*68 + c] = lw[t]; }
  __syncthreads();

  int c4  = (tid & 15)*4;
  int bg  = tid >> 4;
  float acc2[4];
  #pragma unroll
  for(int q=0;q<4;q++) acc2[q] = lb[c4+q];
  const float* Ys = ysig + bg*CTOT;
  #pragma unroll 8
  for(int o2=0; o2<CTOT; o2++){
    float4 w4 = *(const float4*)(lwT + o2*68 + c4);
    float y = Ys[o2];
    acc2[0] += y*w4.x; acc2[1] += y*w4.y; acc2[2] += y*w4.z; acc2[3] += y*w4.w;
  }
  *(float4*)(g_Z + (size_t)n*BZ + bg*CO + c4) = make_float4(acc2[0],acc2[1],acc2[2],acc2[3]);
}

// ---------------- K9: upd final ----------------
__global__ void __launch_bounds__(256) k_upd_final(const float* __restrict__ E,
                                                   const float* __restrict__ ubp,
                                                   float* __restrict__ out){
  __shared__ float Xs[3*1024];
  __shared__ float Zs[3*1024];
  __shared__ float bias[CO];
  int n = blockIdx.x, tid = threadIdx.x;
  {
    const float* s0 = g_IAS + (size_t)n*BC;
    const float* s1 = g_XG1 + (size_t)n*BC;
    const float* s2 = g_XG2 + (size_t)n*BC;
    int b = tid >> 4, f = (tid & 15)*4;
    ((float4*)(Xs       ))[tid] = *(const float4*)(s0 + b*CTOT + f);
    ((float4*)(Xs + 1024))[tid] = *(const float4*)(s1 + b*CTOT + f);
    ((float4*)(Xs + 2048))[tid] = *(const float4*)(s2 + b*CTOT + f);
    ((float4*)(Zs       ))[tid] = ((const float4*)(g_Z   + (size_t)n*BZ))[tid];
    ((float4*)(Zs + 1024))[tid] = ((const float4*)(g_ZG1 + (size_t)n*BZ))[tid];
    ((float4*)(Zs + 2048))[tid] = ((const float4*)(g_ZG2 + (size_t)n*BZ))[tid];
  }
  if(tid < CO){
    float b = 0.f;
    #pragma unroll
    for(int d=0; d<DEMB; d++) b += E[n*DEMB + d]*ubp[d*CO + tid];
    bias[tid] = b;
  }
  __syncthreads();

  int oq = (tid & 15)*4;
  int bg = tid >> 4;
  float acc[4];
  #pragma unroll
  for(int q=0;q<4;q++) acc[q] = bias[oq+q];

  const float* W = g_Wu + (size_t)n*JU + oq;
  #pragma unroll
  for(int k=0; k<3; k++){
    const float* Xk = Xs + k*1024 + bg*CO;
    const float* Zk = Zs + k*1024 + bg*CO;
    const float* Wk = W + (size_t)k*128*CO;
    #pragma unroll 8
    for(int i=0; i<64; i++){
      float4 w4 = *(const float4*)(Wk + (size_t)i*CO);
      float x = Xk[i];
      acc[0] += x*w4.x; acc[1] += x*w4.y; acc[2] += x*w4.z; acc[3] += x*w4.w;
    }
    const float* Wk2 = Wk + (size_t)64*CO;
    #pragma unroll 8
    for(int i=0; i<64; i++){
      float4 w4 = *(const float4*)(Wk2 + (size_t)i*CO);
      float z = Zk[i];
      acc[0] += z*w4.x; acc[1] += z*w4.y; acc[2] += z*w4.z; acc[3] += z*w4.w;
    }
  }
  float4 v = make_float4(tanhf(acc[0]), tanhf(acc[1]), tanhf(acc[2]), tanhf(acc[3]));
  *(float4*)(out + ((size_t)bg*NN + n)*CO + oq) = v;
}

// ---------------- launch ----------------
extern "C" void kernel_launch(void* const* d_in, const int* in_sizes, int n_in,
                              void* d_out, int out_size){
  (void)in_sizes; (void)n_in; (void)out_size;
  const float* x   = (const float*)d_in[0];
  const float* st  = (const float*)d_in[1];
  const float* E   = (const float*)d_in[2];
  const float* gwp = (const float*)d_in[3];
  const float* gbp = (const float*)d_in[4];
  const float* uwp = (const float*)d_in[5];
  const float* ubp = (const float*)d_in[6];
  const float* lw  = (const float*)d_in[7];
  const float* lb  = (const float*)d_in[8];
  float* out = (float*)d_out;

  static cudaStream_t sSide = 0;
  static cudaEvent_t evFork = 0, evJoin = 0;
  static int init_done = 0;
  if(!init_done){
    cudaFuncSetAttribute(mma_gemm<0,1,128>, cudaFuncAttributeMaxDynamicSharedMemorySize, SM_128);
    cudaFuncSetAttribute(mma_gemm<1,0,128>, cudaFuncAttributeMaxDynamicSharedMemorySize, SM_128);
    cudaFuncSetAttribute(mma_gemm<0,1,64>,  cudaFuncAttributeMaxDynamicSharedMemorySize, SM_64);
    cudaFuncSetAttribute(mma_gemm<1,0,64>,  cudaFuncAttributeMaxDynamicSharedMemorySize, SM_64);
    cudaStreamCreateWithFlags(&sSide, cudaStreamNonBlocking);
    cudaEventCreateWithFlags(&evFork, cudaEventDisableTiming);
    cudaEventCreateWithFlags(&evJoin, cudaEventDisableTiming);
    init_done = 1;
  }

  k_supports<<<NN, 256>>>(E);
  k_pack<<<(NN*BC/4)/256, 256>>>(x, st);
  k_cvtT<<<dim3(BC/32, NN/32), 256>>>(0, BC, 0);                            // IAS -> Ta

  // launch 4 (profiled): big GEMM1
  mma_gemm<0,1,128><<<dim3(BC/128, NN/128), 256, SM_128>>>(1, 0, BC, 0, 2); // XG1; T->Tb

  cudaEventRecord(evFork, 0);
  cudaStreamWaitEvent(sSide, evFork, 0);
  k_wcombine<<<dim3(JG/1024, NN/32), 256, 0, sSide>>>(E, gwp, JG, 0);
  k_wcombine<<<dim3(JU/1024, NN/32), 256, 0, sSide>>>(E, uwp, JU, 1);
  cudaEventRecord(evJoin, sSide);

  mma_gemm<1,0,128><<<dim3(BC/128, NN/128), 256, SM_128>>>(2, 0, BC, 2, 0); // XG2

  cudaStreamWaitEvent(0, evJoin, 0);
  k_gate_final<<<NN, 256>>>(E, gbp, lw, lb);                                // -> g_Z

  k_cvtT<<<dim3(BZ/32, NN/32), 256>>>(3, BZ, 0);                            // Z -> Ta
  mma_gemm<0,1,64><<<dim3(BZ/128, NN/64), 256, SM_64>>>(4, 3, BZ, 0, 2);    // ZG1; T->Tb
  mma_gemm<1,0,64><<<dim3(BZ/128, NN/64), 256, SM_64>>>(5, 3, BZ, 2, 0);    // ZG2

  k_upd_final<<<NN, 256>>>(E, ubp, out);                                    // -> hc
}

// round 15
// speedup vs baseline: 1.3881x; 1.1456x over previous
#include <cuda_runtime.h>
#include <cuda_fp16.h>
#include <math.h>
#include <stdint.h>

#define NN    2048
#define BATCH 16
#define DEMB  10
#define CTOT  128
#define CO    64
#define BC    (BATCH*CTOT)   // 2048
#define BZ    (BATCH*CO)     // 1024
#define KC    (3*CTOT)       // 384
#define JG    (KC*CTOT)      // 49152
#define JU    (KC*CO)        // 24576

// ---------------- device scratch ----------------
__device__ float g_IAS[(size_t)NN*BC];
__device__ float g_XG1[(size_t)NN*BC];
__device__ float g_XG2[(size_t)NN*BC];
__device__ float g_Z  [(size_t)NN*BZ];
__device__ float g_ZG1[(size_t)NN*BZ];
__device__ float g_ZG2[(size_t)NN*BZ];
__device__ __align__(256) __half g_Wg [(size_t)NN*JG];
__device__ __align__(256) __half g_Wu [(size_t)NN*JU];
__device__ __align__(256) __half g_Sh [(size_t)NN*NN];
__device__ __align__(256) __half g_TaH[(size_t)NN*NN];
__device__ __align__(256) __half g_TaL[(size_t)NN*NN];
__device__ __align__(256) __half g_TbH[(size_t)NN*NN];
__device__ __align__(256) __half g_TbL[(size_t)NN*NN];

// ---------------- pickers ----------------
__device__ __forceinline__ const float* pickIn(int id){
  switch(id){ case 0: return g_IAS; case 1: return g_XG1; case 2: return g_XG2;
              case 3: return g_Z;   case 4: return g_ZG1; }
  return g_IAS;
}
__device__ __forceinline__ float* pickOut(int id){
  switch(id){ case 1: return g_XG1; case 2: return g_XG2;
              case 4: return g_ZG1; case 5: return g_ZG2; }
  return g_XG1;
}
__device__ __forceinline__ __half* pickHF(int id){
  switch(id){ case 0: return g_TaH; case 1: return g_TaL;
              case 2: return g_TbH; case 3: return g_TbL; }
  return g_TaH;
}

// ---------------- warp reductions ----------------
__device__ __forceinline__ float warpMax(float v){
  #pragma unroll
  for(int o=16;o;o>>=1) v = fmaxf(v, __shfl_xor_sync(0xffffffffu, v, o));
  return v;
}
__device__ __forceinline__ float warpSum(float v){
  #pragma unroll
  for(int o=16;o;o>>=1) v += __shfl_xor_sync(0xffffffffu, v, o);
  return v;
}

// ---------------- PTX helpers ----------------
__device__ __forceinline__ uint32_t smem_u32(const void* p){
  uint32_t a;
  asm("{ .reg .u64 t; cvta.to.shared.u64 t, %1; cvt.u32.u64 %0, t; }" : "=r"(a) : "l"(p));
  return a;
}
__device__ __forceinline__ void cp16(uint32_t s, const void* g){
  asm volatile("cp.async.cg.shared.global [%0], [%1], 16;" :: "r"(s), "l"(g) : "memory");
}
__device__ __forceinline__ void cp_commit(){ asm volatile("cp.async.commit_group;" ::: "memory"); }
__device__ __forceinline__ void ldsm_x4(uint32_t* r, uint32_t a){
  asm volatile("ldmatrix.sync.aligned.m8n8.x4.shared.b16 {%0,%1,%2,%3}, [%4];"
    : "=r"(r[0]),"=r"(r[1]),"=r"(r[2]),"=r"(r[3]) : "r"(a));
}
__device__ __forceinline__ void mma16816(float* d, const uint32_t* a, const uint32_t* b){
  asm volatile("mma.sync.aligned.m16n8k16.row.col.f32.f16.f16.f32 "
    "{%0,%1,%2,%3}, {%4,%5,%6,%7}, {%8,%9}, {%0,%1,%2,%3};"
    : "+f"(d[0]),"+f"(d[1]),"+f"(d[2]),"+f"(d[3])
    : "r"(a[0]),"r"(a[1]),"r"(a[2]),"r"(a[3]), "r"(b[0]),"r"(b[1]));
}

// ---------------- K1: S row softmax -> fp16 ----------------
__global__ void __launch_bounds__(256) k_supports(const float* __restrict__ E){
  __shared__ float sh[8];
  __shared__ float bcast;
  int row = blockIdx.x, tid = threadIdx.x;
  float Er[DEMB];
  #pragma unroll
  for(int d=0; d<DEMB; d++) Er[d] = E[row*DEMB + d];
  float a[8], m = -1e30f;
  #pragma unroll
  for(int q=0; q<8; q++){
    int col = tid + q*256;
    const float* Ec = E + (size_t)col*DEMB;
    float s = 0.f;
    #pragma unroll
    for(int d=0; d<DEMB; d++) s += Er[d]*Ec[d];
    s = fmaxf(s, 0.f);
    a[q] = s; m = fmaxf(m, s);
  }
  m = warpMax(m);
  if((tid&31)==0) sh[tid>>5] = m;
  __syncthreads();
  if(tid<32){ float t = (tid<8)? sh[tid] : -1e30f; t = warpMax(t); if(tid==0) bcast = t; }
  __syncthreads();
  m = bcast;
  float ssum = 0.f;
  #pragma unroll
  for(int q=0; q<8; q++){ a[q] = expf(a[q]-m); ssum += a[q]; }
  ssum = warpSum(ssum);
  __syncthreads();
  if((tid&31)==0) sh[tid>>5] = ssum;
  __syncthreads();
  if(tid<32){ float t = (tid<8)? sh[tid] : 0.f; t = warpSum(t); if(tid==0) bcast = t; }
  __syncthreads();
  float inv = 1.f/bcast;
  #pragma unroll
  for(int q=0; q<8; q++)
    g_Sh[(size_t)row*NN + tid + q*256] = __float2half_rn(a[q]*inv);
}

// ---------------- K2: pack IAS ----------------
__global__ void __launch_bounds__(256) k_pack(const float* __restrict__ x,
                                              const float* __restrict__ st){
  int t = blockIdx.x*256 + threadIdx.x;
  int e = t*4;
  int n = e >> 11;
  int r = e & 2047;
  int b = r >> 7;
  int c = r & 127;
  float4 v;
  if (c < 64) v = *(const float4*)(x  + ((size_t)b*NN + n)*64 + c);
  else        v = *(const float4*)(st + ((size_t)b*NN + n)*64 + (c-64));
  *(float4*)(g_IAS + e) = v;
}

// -------- convert+transpose fp32 [2048 x W] -> fp16 hi/lo [W x 2048] --------
__global__ void __launch_bounds__(256) k_cvtT(int srcId, int W, int dstHi){
  const float* src = pickIn(srcId);
  __half* dH = pickHF(dstHi);
  __half* dL = pickHF(dstHi+1);
  __shared__ float t[32][33];
  int tx = threadIdx.x & 31, ty = threadIdx.x >> 5;
  int c0 = blockIdx.x*32, r0 = blockIdx.y*32;
  #pragma unroll
  for(int j=0;j<4;j++)
    t[ty+8*j][tx] = src[(size_t)(r0+ty+8*j)*W + c0+tx];
  __syncthreads();
  #pragma unroll
  for(int j=0;j<4;j++){
    float v = t[tx][ty+8*j];
    __half hi = __float2half_rn(v);
    __half lo = __float2half_rn(v - __half2float(hi));
    size_t o = (size_t)(c0+ty+8*j)*NN + r0 + tx;
    dH[o] = hi; dL[o] = lo;
  }
}

// ---------------- K5: wcombine -> fp16 W ----------------
__global__ void __launch_bounds__(256) k_wcombine(const float* __restrict__ E,
                                                  const float* __restrict__ wp,
                                                  int J, int which){
  __half* out = which ? g_Wu : g_Wg;
  int j  = (blockIdx.x*256 + threadIdx.x)*4;
  int n0 = blockIdx.y*32;
  float4 w[DEMB];
  #pragma unroll
  for(int d=0; d<DEMB; d++) w[d] = *(const float4*)(wp + (size_t)d*J + j);
  __shared__ float Es[32*DEMB];
  for(int t=threadIdx.x; t<32*DEMB; t+=256) Es[t] = E[n0*DEMB + t];
  __syncthreads();
  #pragma unroll 2
  for(int nn=0; nn<32; nn++){
    float4 a = make_float4(0.f,0.f,0.f,0.f);
    #pragma unroll
    for(int d=0; d<DEMB; d++){
      float e = Es[nn*DEMB+d];
      a.x += e*w[d].x; a.y += e*w[d].y; a.z += e*w[d].z; a.w += e*w[d].w;
    }
    __half h[4];
    h[0] = __float2half_rn(a.x); h[1] = __float2half_rn(a.y);
    h[2] = __float2half_rn(a.z); h[3] = __float2half_rn(a.w);
    *(uint2*)(out + (size_t)(n0+nn)*J + j) = *(uint2*)h;
  }
}

// ---------------- HMMA fp16x2 GEMM ----------------
#define PITCH    48

template<int MODE, int WRITE_T, int TM>
__global__ void __launch_bounds__(256,2) mma_gemm(int cId, int dId, int Ncols,
                                                  int bHiId, int tHiId){
  constexpr int WM   = (TM == 128) ? 4 : 2;
  constexpr int WN   = 8 / WM;
  constexpr int NT   = (128 / WN) / 8;
  constexpr int NTP  = NT / 2;
  constexpr int A_T  = TM * PITCH;
  constexpr int B_T  = 128 * PITCH;
  constexpr int STG  = A_T + 2*B_T;
  constexpr int NTRANS = (TM + 2*128) * 2;
  constexpr int NU   = (NTRANS + 255) / 256;

  extern __shared__ char smem[];
  float*       C = pickOut(cId);
  const float* D = pickIn(dId);
  const __half* Bh = pickHF(bHiId);
  const __half* Bl = pickHF(bHiId+1);
  const uint32_t sb = smem_u32(smem);
  const int tid = threadIdx.x, wid = tid >> 5, lane = tid & 31;
  const int warpM = wid % WM, warpN = wid / WM;
  const size_t row0 = (size_t)blockIdx.y * TM;
  const size_t n0   = (size_t)blockIdx.x * 128;

  float acc[2][NT][4];
  #pragma unroll
  for(int m=0;m<2;m++)
    #pragma unroll
    for(int n=0;n<NT;n++)
      #pragma unroll
      for(int q=0;q<4;q++) acc[m][n][q] = 0.f;

  auto issue = [&](int c){
    const size_t kb = (size_t)c * 16;
    const uint32_t bo = sb + (uint32_t)(c & 3) * STG;
    #pragma unroll
    for(int u = 0; u < NU; u++){
      int e  = tid + u*256;
      if(NTRANS % 256 != 0 && e >= NTRANS) break;
      int h  = e & 1;
      int rr = e >> 1;
      if(rr < TM){
        cp16(bo + rr*PITCH + h*16, g_Sh + (row0 + rr)*(size_t)NN + kb + h*8);
      } else if(rr < TM + 128){
        int r = rr - TM;
        cp16(bo + A_T + r*PITCH + h*16, Bh + (n0 + r)*(size_t)NN + kb + h*8);
      } else {
        int r = rr - TM - 128;
        cp16(bo + A_T + B_T + r*PITCH + h*16, Bl + (n0 + r)*(size_t)NN + kb + h*8);
      }
    }
    cp_commit();
  };

  issue(0); issue(1); issue(2);

  const uint32_t aoff = (uint32_t)((warpM*32 + (lane & 15))*PITCH + (lane >> 4)*16);
  const uint32_t boff = (uint32_t)(A_T + (warpN*(NT*8) + ((lane >> 4) & 1)*8 + (lane & 7))*PITCH
                                   + ((lane >> 3) & 1)*16);

  for(int c=0; c<128; c++){
    if(c <= 125)      asm volatile("cp.async.wait_group 2;" ::: "memory");
    else if(c == 126) asm volatile("cp.async.wait_group 1;" ::: "memory");
    else              asm volatile("cp.async.wait_group 0;" ::: "memory");
    __syncthreads();
    if(c + 3 < 128) issue(c+3);

    const uint32_t bo = sb + (uint32_t)(c & 3) * STG;
    uint32_t af[2][4];
    #pragma unroll
    for(int mt=0; mt<2; mt++)
      ldsm_x4(af[mt], bo + aoff + (uint32_t)(mt*16*PITCH));
    #pragma unroll
    for(int ntp=0; ntp<NTP; ntp++){
      uint32_t bd = bo + boff + (uint32_t)(ntp*16*PITCH);
      uint32_t bH[4], bL[4];
      ldsm_x4(bH, bd);
      ldsm_x4(bL, bd + B_T);
      mma16816(acc[0][2*ntp],   af[0], bH);
      mma16816(acc[1][2*ntp],   af[1], bH);
      mma16816(acc[0][2*ntp+1], af[0], bH+2);
      mma16816(acc[1][2*ntp+1], af[1], bH+2);
      mma16816(acc[0][2*ntp],   af[0], bL);
      mma16816(acc[1][2*ntp],   af[1], bL);
      mma16816(acc[0][2*ntp+1], af[0], bL+2);
      mma16816(acc[1][2*ntp+1], af[1], bL+2);
    }
  }

  // ---------------- epilogue ----------------
  const int g = lane >> 2, tg = lane & 3;
  #pragma unroll
  for(int mt=0; mt<2; mt++){
    size_t r0g = row0 + warpM*32 + mt*16 + g;
    #pragma unroll
    for(int nt=0; nt<NT; nt++){
      size_t col = n0 + warpN*(NT*8) + nt*8 + tg*2;
      size_t o0 = r0g      *(size_t)Ncols + col;
      size_t o1 = (r0g + 8)*(size_t)Ncols + col;
      float2 v0 = make_float2(acc[mt][nt][0], acc[mt][nt][1]);
      float2 v1 = make_float2(acc[mt][nt][2], acc[mt][nt][3]);
      if(MODE == 1){
        float2 d0 = *(const float2*)(D + o0);
        float2 d1 = *(const float2*)(D + o1);
        v0.x = 2.f*v0.x - d0.x; v0.y = 2.f*v0.y - d0.y;
        v1.x = 2.f*v1.x - d1.x; v1.y = 2.f*v1.y - d1.y;
      }
      *(float2*)(C + o0) = v0;
      *(float2*)(C + o1) = v1;
    }
  }

  if(WRITE_T){
    __half* TH = pickHF(tHiId);
    __half* TL = pickHF(tHiId+1);
    float* tile = (float*)smem;          // [TM][132]
    __syncthreads();
    #pragma unroll
    for(int mt=0; mt<2; mt++){
      int rr = warpM*32 + mt*16 + g;
      #pragma unroll
      for(int nt=0; nt<NT; nt++){
        int cc = warpN*(NT*8) + nt*8 + tg*2;
        tile[rr*132 + cc]         = acc[mt][nt][0];
        tile[rr*132 + cc + 1]     = acc[mt][nt][1];
        tile[(rr+8)*132 + cc]     = acc[mt][nt][2];
        tile[(rr+8)*132 + cc + 1] = acc[mt][nt][3];
      }
    }
    __syncthreads();
    int c0 = tid >> 1, half_ = tid & 1;
    size_t baseO = (size_t)(n0 + c0)*NN + row0 + half_*(TM/2);
    #pragma unroll
    for(int ch=0; ch<TM/16; ch++){
      __half hb[8], lb8[8];
      #pragma unroll
      for(int e=0; e<8; e++){
        float v = tile[(half_*(TM/2) + ch*8 + e)*132 + c0];
        __half hi = __float2half_rn(v);
        hb[e] = hi;
        lb8[e] = __float2half_rn(v - __half2float(hi));
      }
      *(uint4*)(TH + baseO + ch*8) = *(uint4*)hb;
      *(uint4*)(TL + baseO + ch*8) = *(uint4*)lb8;
    }
  }
}

#define SM_128  (4*((128*PITCH) + 2*(128*PITCH)))   // 73728
#define SM_64   (4*((64*PITCH)  + 2*(128*PITCH)))   // 61440

// ---------------- K6: gate final (fp16 Wg) ----------------
__global__ void __launch_bounds__(256) k_gate_final(const float* __restrict__ E,
                                                    const float* __restrict__ gbp,
                                                    const float* __restrict__ lw,
                                                    const float* __restrict__ lb){
  __shared__ float smA[128*68];
  __shared__ float ysig[BATCH*CTOT];
  __shared__ float bias[CTOT];
  int n = blockIdx.x, tid = threadIdx.x;

  float* Xs = smA;
  for(int t=tid; t<512; t+=256){
    ((float4*)Xs)[t]        = ((const float4*)(g_IAS + (size_t)n*BC))[t];
    ((float4*)(Xs+2048))[t] = ((const float4*)(g_XG1 + (size_t)n*BC))[t];
    ((float4*)(Xs+4096))[t] = ((const float4*)(g_XG2 + (size_t)n*BC))[t];
  }
  if(tid < CTOT){
    float b = 0.f;
    #pragma unroll
    for(int d=0; d<DEMB; d++) b += E[n*DEMB + d]*gbp[d*CTOT + tid];
    bias[tid] = b;
  }
  __syncthreads();

  int oq = (tid & 31)*4;
  int b0 = (tid >> 5)*2, b1 = b0 + 1;
  float acc[2][4];
  #pragma unroll
  for(int q=0;q<4;q++){ acc[0][q] = bias[oq+q]; acc[1][q] = bias[oq+q]; }

  const __half* W = g_Wg + (size_t)n*JG + oq;
  #pragma unroll
  for(int k=0; k<3; k++){
    const float* Xk0 = Xs + k*2048 + b0*CTOT;
    const float* Xk1 = Xs + k*2048 + b1*CTOT;
    const __half* Wk = W + (size_t)k*128*CTOT;
    #pragma unroll 8
    for(int i=0; i<128; i++){
      uint2 wv = *(const uint2*)(Wk + (size_t)i*CTOT);
      float2 f0 = __half22float2(*(__half2*)&wv.x);
      float2 f1 = __half22float2(*(__half2*)&wv.y);
      float x0 = Xk0[i], x1 = Xk1[i];
      acc[0][0] += x0*f0.x; acc[0][1] += x0*f0.y; acc[0][2] += x0*f1.x; acc[0][3] += x0*f1.y;
      acc[1][0] += x1*f0.x; acc[1][1] += x1*f0.y; acc[1][2] += x1*f1.x; acc[1][3] += x1*f1.y;
    }
  }
  #pragma unroll
  for(int bb=0; bb<2; bb++){
    float4 v;
    v.x = 1.f/(1.f + expf(-acc[bb][0]));
    v.y = 1.f/(1.f + expf(-acc[bb][1]));
    v.z = 1.f/(1.f + expf(-acc[bb][2]));
    v.w = 1.f/(1.f + expf(-acc[bb][3]));
    *(float4*)(ysig + (b0+bb)*CTOT + oq) = v;
  }
  __syncthreads();

  float* lwT = smA;
  for(int t=tid; t<CO*CTOT; t+=256){ int c = t>>7, oo = t&127; lwT[oo*68 + c] = lw[t]; }
  __syncthreads();

  int c4  = (tid & 15)*4;
  int bg  = tid >> 4;
  float acc2[4];
  #pragma unroll
  for(int q=0;q<4;q++) acc2[q] = lb[c4+q];
  const float* Ys = ysig + bg*CTOT;
  #pragma unroll 8
  for(int o2=0; o2<CTOT; o2++){
    float4 w4 = *(const float4*)(lwT + o2*68 + c4);
    float y = Ys[o2];
    acc2[0] += y*w4.x; acc2[1] += y*w4.y; acc2[2] += y*w4.z; acc2[3] += y*w4.w;
  }
  *(float4*)(g_Z + (size_t)n*BZ + bg*CO + c4) = make_float4(acc2[0],acc2[1],acc2[2],acc2[3]);
}

// ---------------- K9: upd final (fp16 Wu) ----------------
__global__ void __launch_bounds__(256) k_upd_final(const float* __restrict__ E,
                                                   const float* __restrict__ ubp,
                                                   float* __restrict__ out){
  __shared__ float Xs[3*1024];
  __shared__ float Zs[3*1024];
  __shared__ float bias[CO];
  int n = blockIdx.x, tid = threadIdx.x;
  {
    const float* s0 = g_IAS + (size_t)n*BC;
    const float* s1 = g_XG1 + (size_t)n*BC;
    const float* s2 = g_XG2 + (size_t)n*BC;
    int b = tid >> 4, f = (tid & 15)*4;
    ((float4*)(Xs       ))[tid] = *(const float4*)(s0 + b*CTOT + f);
    ((float4*)(Xs + 1024))[tid] = *(const float4*)(s1 + b*CTOT + f);
    ((float4*)(Xs + 2048))[tid] = *(const float4*)(s2 + b*CTOT + f);
    ((float4*)(Zs       ))[tid] = ((const float4*)(g_Z   + (size_t)n*BZ))[tid];
    ((float4*)(Zs + 1024))[tid] = ((const float4*)(g_ZG1 + (size_t)n*BZ))[tid];
    ((float4*)(Zs + 2048))[tid] = ((const float4*)(g_ZG2 + (size_t)n*BZ))[tid];
  }
  if(tid < CO){
    float b = 0.f;
    #pragma unroll
    for(int d=0; d<DEMB; d++) b += E[n*DEMB + d]*ubp[d*CO + tid];
    bias[tid] = b;
  }
  __syncthreads();

  int oq = (tid & 15)*4;
  int bg = tid >> 4;
  float acc[4];
  #pragma unroll
  for(int q=0;q<4;q++) acc[q] = bias[oq+q];

  const __half* W = g_Wu + (size_t)n*JU + oq;
  #pragma unroll
  for(int k=0; k<3; k++){
    const float* Xk = Xs + k*1024 + bg*CO;
    const float* Zk = Zs + k*1024 + bg*CO;
    const __half* Wk = W + (size_t)k*128*CO;
    #pragma unroll 8
    for(int i=0; i<64; i++){
      uint2 wv = *(const uint2*)(Wk + (size_t)i*CO);
      float2 f0 = __half22float2(*(__half2*)&wv.x);
      float2 f1 = __half22float2(*(__half2*)&wv.y);
      float x = Xk[i];
      acc[0] += x*f0.x; acc[1] += x*f0.y; acc[2] += x*f1.x; acc[3] += x*f1.y;
    }
    const __half* Wk2 = Wk + (size_t)64*CO;
    #pragma unroll 8
    for(int i=0; i<64; i++){
      uint2 wv = *(const uint2*)(Wk2 + (size_t)i*CO);
      float2 f0 = __half22float2(*(__half2*)&wv.x);
      float2 f1 = __half22float2(*(__half2*)&wv.y);
      float z = Zk[i];
      acc[0] += z*f0.x; acc[1] += z*f0.y; acc[2] += z*f1.x; acc[3] += z*f1.y;
    }
  }
  float4 v = make_float4(tanhf(acc[0]), tanhf(acc[1]), tanhf(acc[2]), tanhf(acc[3]));
  *(float4*)(out + ((size_t)bg*NN + n)*CO + oq) = v;
}

// ---------------- launch ----------------
extern "C" void kernel_launch(void* const* d_in, const int* in_sizes, int n_in,
                              void* d_out, int out_size){
  (void)in_sizes; (void)n_in; (void)out_size;
  const float* x   = (const float*)d_in[0];
  const float* st  = (const float*)d_in[1];
  const float* E   = (const float*)d_in[2];
  const float* gwp = (const float*)d_in[3];
  const float* gbp = (const float*)d_in[4];
  const float* uwp = (const float*)d_in[5];
  const float* ubp = (const float*)d_in[6];
  const float* lw  = (const float*)d_in[7];
  const float* lb  = (const float*)d_in[8];
  float* out = (float*)d_out;

  static cudaStream_t sSide = 0;
  static cudaEvent_t evFork = 0, evJoin = 0;
  static int init_done = 0;
  if(!init_done){
    cudaFuncSetAttribute(mma_gemm<0,1,128>, cudaFuncAttributeMaxDynamicSharedMemorySize, SM_128);
    cudaFuncSetAttribute(mma_gemm<1,0,128>, cudaFuncAttributeMaxDynamicSharedMemorySize, SM_128);
    cudaFuncSetAttribute(mma_gemm<0,1,64>,  cudaFuncAttributeMaxDynamicSharedMemorySize, SM_64);
    cudaFuncSetAttribute(mma_gemm<1,0,64>,  cudaFuncAttributeMaxDynamicSharedMemorySize, SM_64);
    cudaStreamCreateWithFlags(&sSide, cudaStreamNonBlocking);
    cudaEventCreateWithFlags(&evFork, cudaEventDisableTiming);
    cudaEventCreateWithFlags(&evJoin, cudaEventDisableTiming);
    init_done = 1;
  }

  k_supports<<<NN, 256>>>(E);
  k_pack<<<(NN*BC/4)/256, 256>>>(x, st);
  k_cvtT<<<dim3(BC/32, NN/32), 256>>>(0, BC, 0);                            // IAS -> Ta

  // launch 4 (profiled): big GEMM1
  mma_gemm<0,1,128><<<dim3(BC/128, NN/128), 256, SM_128>>>(1, 0, BC, 0, 2); // XG1; T->Tb

  cudaEventRecord(evFork, 0);
  cudaStreamWaitEvent(sSide, evFork, 0);
  k_wcombine<<<dim3(JG/1024, NN/32), 256, 0, sSide>>>(E, gwp, JG, 0);
  k_wcombine<<<dim3(JU/1024, NN/32), 256, 0, sSide>>>(E, uwp, JU, 1);
  cudaEventRecord(evJoin, sSide);

  mma_gemm<1,0,128><<<dim3(BC/128, NN/128), 256, SM_128>>>(2, 0, BC, 2, 0); // XG2

  cudaStreamWaitEvent(0, evJoin, 0);
  k_gate_final<<<NN, 256>>>(E, gbp, lw, lb);                                // -> g_Z

  k_cvtT<<<dim3(BZ/32, NN/32), 256>>>(3, BZ, 0);                            // Z -> Ta
  mma_gemm<0,1,64><<<dim3(BZ/128, NN/64), 256, SM_64>>>(4, 3, BZ, 0, 2);    // ZG1; T->Tb
  mma_gemm<1,0,64><<<dim3(BZ/128, NN/64), 256, SM_64>>>(5, 3, BZ, 2, 0);    // ZG2

  k_upd_final<<<NN, 256>>>(E, ubp, out);                                    // -> hc
}

// round 16
// speedup vs baseline: 1.5344x; 1.1054x over previous
#include <cuda_runtime.h>
#include <cuda_fp16.h>
#include <math.h>
#include <stdint.h>

#define NN    2048
#define BATCH 16
#define DEMB  10
#define CTOT  128
#define CO    64
#define BC    (BATCH*CTOT)   // 2048
#define BZ    (BATCH*CO)     // 1024
#define KC    (3*CTOT)       // 384
#define JG    (KC*CTOT)      // 49152
#define JU    (KC*CO)        // 24576

// ---------------- device scratch ----------------
__device__ float g_IAS[(size_t)NN*BC];
__device__ float g_XG1[(size_t)NN*BC];
__device__ float g_XG2[(size_t)NN*BC];
__device__ float g_Z  [(size_t)NN*BZ];
__device__ float g_ZG1[(size_t)NN*BZ];
__device__ float g_ZG2[(size_t)NN*BZ];
__device__ __align__(256) __half g_Wg [(size_t)NN*JG];
__device__ __align__(256) __half g_Wu [(size_t)NN*JU];
__device__ __align__(256) __half g_Sh [(size_t)NN*NN];
__device__ __align__(256) __half g_TaH[(size_t)NN*NN];
__device__ __align__(256) __half g_TaL[(size_t)NN*NN];
__device__ __align__(256) __half g_TbH[(size_t)NN*NN];
__device__ __align__(256) __half g_TbL[(size_t)NN*NN];

// ---------------- pickers ----------------
__device__ __forceinline__ const float* pickIn(int id){
  switch(id){ case 0: return g_IAS; case 1: return g_XG1; case 2: return g_XG2;
              case 3: return g_Z;   case 4: return g_ZG1; }
  return g_IAS;
}
__device__ __forceinline__ float* pickOut(int id){
  switch(id){ case 1: return g_XG1; case 2: return g_XG2;
              case 4: return g_ZG1; case 5: return g_ZG2; }
  return g_XG1;
}
__device__ __forceinline__ __half* pickHF(int id){
  switch(id){ case 0: return g_TaH; case 1: return g_TaL;
              case 2: return g_TbH; case 3: return g_TbL; }
  return g_TaH;
}

// ---------------- warp reductions ----------------
__device__ __forceinline__ float warpMax(float v){
  #pragma unroll
  for(int o=16;o;o>>=1) v = fmaxf(v, __shfl_xor_sync(0xffffffffu, v, o));
  return v;
}
__device__ __forceinline__ float warpSum(float v){
  #pragma unroll
  for(int o=16;o;o>>=1) v += __shfl_xor_sync(0xffffffffu, v, o);
  return v;
}

// ---------------- PTX helpers ----------------
__device__ __forceinline__ uint32_t smem_u32(const void* p){
  uint32_t a;
  asm("{ .reg .u64 t; cvta.to.shared.u64 t, %1; cvt.u32.u64 %0, t; }" : "=r"(a) : "l"(p));
  return a;
}
__device__ __forceinline__ void cp16(uint32_t s, const void* g){
  asm volatile("cp.async.cg.shared.global [%0], [%1], 16;" :: "r"(s), "l"(g) : "memory");
}
__device__ __forceinline__ void cp_commit(){ asm volatile("cp.async.commit_group;" ::: "memory"); }
__device__ __forceinline__ void ldsm_x4(uint32_t* r, uint32_t a){
  asm volatile("ldmatrix.sync.aligned.m8n8.x4.shared.b16 {%0,%1,%2,%3}, [%4];"
    : "=r"(r[0]),"=r"(r[1]),"=r"(r[2]),"=r"(r[3]) : "r"(a));
}
__device__ __forceinline__ void mma16816(float* d, const uint32_t* a, const uint32_t* b){
  asm volatile("mma.sync.aligned.m16n8k16.row.col.f32.f16.f16.f32 "
    "{%0,%1,%2,%3}, {%4,%5,%6,%7}, {%8,%9}, {%0,%1,%2,%3};"
    : "+f"(d[0]),"+f"(d[1]),"+f"(d[2]),"+f"(d[3])
    : "r"(a[0]),"r"(a[1]),"r"(a[2]),"r"(a[3]), "r"(b[0]),"r"(b[1]));
}

// ---------------- K1: S row softmax -> fp16 ----------------
__global__ void __launch_bounds__(256) k_supports(const float* __restrict__ E){
  __shared__ float sh[8];
  __shared__ float bcast;
  int row = blockIdx.x, tid = threadIdx.x;
  float Er[DEMB];
  #pragma unroll
  for(int d=0; d<DEMB; d++) Er[d] = E[row*DEMB + d];
  float a[8], m = -1e30f;
  #pragma unroll
  for(int q=0; q<8; q++){
    int col = tid + q*256;
    const float* Ec = E + (size_t)col*DEMB;
    float s = 0.f;
    #pragma unroll
    for(int d=0; d<DEMB; d++) s += Er[d]*Ec[d];
    s = fmaxf(s, 0.f);
    a[q] = s; m = fmaxf(m, s);
  }
  m = warpMax(m);
  if((tid&31)==0) sh[tid>>5] = m;
  __syncthreads();
  if(tid<32){ float t = (tid<8)? sh[tid] : -1e30f; t = warpMax(t); if(tid==0) bcast = t; }
  __syncthreads();
  m = bcast;
  float ssum = 0.f;
  #pragma unroll
  for(int q=0; q<8; q++){ a[q] = expf(a[q]-m); ssum += a[q]; }
  ssum = warpSum(ssum);
  __syncthreads();
  if((tid&31)==0) sh[tid>>5] = ssum;
  __syncthreads();
  if(tid<32){ float t = (tid<8)? sh[tid] : 0.f; t = warpSum(t); if(tid==0) bcast = t; }
  __syncthreads();
  float inv = 1.f/bcast;
  #pragma unroll
  for(int q=0; q<8; q++)
    g_Sh[(size_t)row*NN + tid + q*256] = __float2half_rn(a[q]*inv);
}

// ---------------- K2: pack IAS ----------------
__global__ void __launch_bounds__(256) k_pack(const float* __restrict__ x,
                                              const float* __restrict__ st){
  int t = blockIdx.x*256 + threadIdx.x;
  int e = t*4;
  int n = e >> 11;
  int r = e & 2047;
  int b = r >> 7;
  int c = r & 127;
  float4 v;
  if (c < 64) v = *(const float4*)(x  + ((size_t)b*NN + n)*64 + c);
  else        v = *(const float4*)(st + ((size_t)b*NN + n)*64 + (c-64));
  *(float4*)(g_IAS + e) = v;
}

// -------- convert+transpose fp32 [2048 x W] -> fp16 hi/lo [W x 2048] --------
__global__ void __launch_bounds__(256) k_cvtT(int srcId, int W, int dstHi){
  const float* src = pickIn(srcId);
  __half* dH = pickHF(dstHi);
  __half* dL = pickHF(dstHi+1);
  __shared__ float t[32][33];
  int tx = threadIdx.x & 31, ty = threadIdx.x >> 5;
  int c0 = blockIdx.x*32, r0 = blockIdx.y*32;
  #pragma unroll
  for(int j=0;j<4;j++)
    t[ty+8*j][tx] = src[(size_t)(r0+ty+8*j)*W + c0+tx];
  __syncthreads();
  #pragma unroll
  for(int j=0;j<4;j++){
    float v = t[tx][ty+8*j];
    __half hi = __float2half_rn(v);
    __half lo = __float2half_rn(v - __half2float(hi));
    size_t o = (size_t)(c0+ty+8*j)*NN + r0 + tx;
    dH[o] = hi; dL[o] = lo;
  }
}

// ---------------- K5: wcombine -> fp16 W ----------------
__global__ void __launch_bounds__(256) k_wcombine(const float* __restrict__ E,
                                                  const float* __restrict__ wp,
                                                  int J, int which){
  __half* out = which ? g_Wu : g_Wg;
  int j  = (blockIdx.x*256 + threadIdx.x)*4;
  int n0 = blockIdx.y*32;
  float4 w[DEMB];
  #pragma unroll
  for(int d=0; d<DEMB; d++) w[d] = *(const float4*)(wp + (size_t)d*J + j);
  __shared__ float Es[32*DEMB];
  for(int t=threadIdx.x; t<32*DEMB; t+=256) Es[t] = E[n0*DEMB + t];
  __syncthreads();
  #pragma unroll 2
  for(int nn=0; nn<32; nn++){
    float4 a = make_float4(0.f,0.f,0.f,0.f);
    #pragma unroll
    for(int d=0; d<DEMB; d++){
      float e = Es[nn*DEMB+d];
      a.x += e*w[d].x; a.y += e*w[d].y; a.z += e*w[d].z; a.w += e*w[d].w;
    }
    __half h[4];
    h[0] = __float2half_rn(a.x); h[1] = __float2half_rn(a.y);
    h[2] = __float2half_rn(a.z); h[3] = __float2half_rn(a.w);
    *(uint2*)(out + (size_t)(n0+nn)*J + j) = *(uint2*)h;
  }
}

// ---------------- HMMA fp16 GEMM, NPROD B-products ----------------
#define PITCH    48

template<int MODE, int WRITE_T, int TM, int NPROD>
__global__ void __launch_bounds__(256,2) mma_gemm(int cId, int dId, int Ncols,
                                                  int bHiId, int tHiId){
  constexpr int WM   = (TM == 128) ? 4 : 2;
  constexpr int WN   = 8 / WM;
  constexpr int NT   = (128 / WN) / 8;
  constexpr int NTP  = NT / 2;
  constexpr int A_T  = TM * PITCH;
  constexpr int B_T  = 128 * PITCH;
  constexpr int STG  = A_T + NPROD*B_T;
  constexpr int NTRANS = (TM + NPROD*128) * 2;
  constexpr int NU   = (NTRANS + 255) / 256;

  extern __shared__ char smem[];
  float*       C = pickOut(cId);
  const float* D = pickIn(dId);
  const __half* Bh = pickHF(bHiId);
  const __half* Bl = pickHF(bHiId+1);
  const uint32_t sb = smem_u32(smem);
  const int tid = threadIdx.x, wid = tid >> 5, lane = tid & 31;
  const int warpM = wid % WM, warpN = wid / WM;
  const size_t row0 = (size_t)blockIdx.y * TM;
  const size_t n0   = (size_t)blockIdx.x * 128;

  float acc[2][NT][4];
  #pragma unroll
  for(int m=0;m<2;m++)
    #pragma unroll
    for(int n=0;n<NT;n++)
      #pragma unroll
      for(int q=0;q<4;q++) acc[m][n][q] = 0.f;

  auto issue = [&](int c){
    const size_t kb = (size_t)c * 16;
    const uint32_t bo = sb + (uint32_t)(c & 3) * STG;
    #pragma unroll
    for(int u = 0; u < NU; u++){
      int e  = tid + u*256;
      if(NTRANS % 256 != 0 && e >= NTRANS) break;
      int h  = e & 1;
      int rr = e >> 1;
      if(rr < TM){
        cp16(bo + rr*PITCH + h*16, g_Sh + (row0 + rr)*(size_t)NN + kb + h*8);
      } else if(rr < TM + 128){
        int r = rr - TM;
        cp16(bo + A_T + r*PITCH + h*16, Bh + (n0 + r)*(size_t)NN + kb + h*8);
      } else if(NPROD == 2){
        int r = rr - TM - 128;
        cp16(bo + A_T + B_T + r*PITCH + h*16, Bl + (n0 + r)*(size_t)NN + kb + h*8);
      }
    }
    cp_commit();
  };

  issue(0); issue(1); issue(2);

  const uint32_t aoff = (uint32_t)((warpM*32 + (lane & 15))*PITCH + (lane >> 4)*16);
  const uint32_t boff = (uint32_t)(A_T + (warpN*(NT*8) + ((lane >> 4) & 1)*8 + (lane & 7))*PITCH
                                   + ((lane >> 3) & 1)*16);

  for(int c=0; c<128; c++){
    if(c <= 125)      asm volatile("cp.async.wait_group 2;" ::: "memory");
    else if(c == 126) asm volatile("cp.async.wait_group 1;" ::: "memory");
    else              asm volatile("cp.async.wait_group 0;" ::: "memory");
    __syncthreads();
    if(c + 3 < 128) issue(c+3);

    const uint32_t bo = sb + (uint32_t)(c & 3) * STG;
    uint32_t af[2][4];
    #pragma unroll
    for(int mt=0; mt<2; mt++)
      ldsm_x4(af[mt], bo + aoff + (uint32_t)(mt*16*PITCH));
    #pragma unroll
    for(int ntp=0; ntp<NTP; ntp++){
      uint32_t bd = bo + boff + (uint32_t)(ntp*16*PITCH);
      uint32_t bH[4];
      ldsm_x4(bH, bd);
      mma16816(acc[0][2*ntp],   af[0], bH);
      mma16816(acc[1][2*ntp],   af[1], bH);
      mma16816(acc[0][2*ntp+1], af[0], bH+2);
      mma16816(acc[1][2*ntp+1], af[1], bH+2);
      if(NPROD == 2){
        uint32_t bL[4];
        ldsm_x4(bL, bd + B_T);
        mma16816(acc[0][2*ntp],   af[0], bL);
        mma16816(acc[1][2*ntp],   af[1], bL);
        mma16816(acc[0][2*ntp+1], af[0], bL+2);
        mma16816(acc[1][2*ntp+1], af[1], bL+2);
      }
    }
  }

  // ---------------- epilogue ----------------
  const int g = lane >> 2, tg = lane & 3;
  #pragma unroll
  for(int mt=0; mt<2; mt++){
    size_t r0g = row0 + warpM*32 + mt*16 + g;
    #pragma unroll
    for(int nt=0; nt<NT; nt++){
      size_t col = n0 + warpN*(NT*8) + nt*8 + tg*2;
      size_t o0 = r0g      *(size_t)Ncols + col;
      size_t o1 = (r0g + 8)*(size_t)Ncols + col;
      float2 v0 = make_float2(acc[mt][nt][0], acc[mt][nt][1]);
      float2 v1 = make_float2(acc[mt][nt][2], acc[mt][nt][3]);
      if(MODE == 1){
        float2 d0 = *(const float2*)(D + o0);
        float2 d1 = *(const float2*)(D + o1);
        v0.x = 2.f*v0.x - d0.x; v0.y = 2.f*v0.y - d0.y;
        v1.x = 2.f*v1.x - d1.x; v1.y = 2.f*v1.y - d1.y;
      }
      *(float2*)(C + o0) = v0;
      *(float2*)(C + o1) = v1;
    }
  }

  if(WRITE_T){
    __half* TH = pickHF(tHiId);
    __half* TL = pickHF(tHiId+1);
    float* tile = (float*)smem;          // [TM][132]
    __syncthreads();
    #pragma unroll
    for(int mt=0; mt<2; mt++){
      int rr = warpM*32 + mt*16 + g;
      #pragma unroll
      for(int nt=0; nt<NT; nt++){
        int cc = warpN*(NT*8) + nt*8 + tg*2;
        tile[rr*132 + cc]         = acc[mt][nt][0];
        tile[rr*132 + cc + 1]     = acc[mt][nt][1];
        tile[(rr+8)*132 + cc]     = acc[mt][nt][2];
        tile[(rr+8)*132 + cc + 1] = acc[mt][nt][3];
      }
    }
    __syncthreads();
    int c0 = tid >> 1, half_ = tid & 1;
    size_t baseO = (size_t)(n0 + c0)*NN + row0 + half_*(TM/2);
    #pragma unroll
    for(int ch=0; ch<TM/16; ch++){
      __half hb[8], lb8[8];
      #pragma unroll
      for(int e=0; e<8; e++){
        float v = tile[(half_*(TM/2) + ch*8 + e)*132 + c0];
        __half hi = __float2half_rn(v);
        hb[e] = hi;
        lb8[e] = __float2half_rn(v - __half2float(hi));
      }
      *(uint4*)(TH + baseO + ch*8) = *(uint4*)hb;
      *(uint4*)(TL + baseO + ch*8) = *(uint4*)lb8;
    }
  }
}

#define SM_128_2  (4*((128*PITCH) + 2*(128*PITCH)))   // 73728
#define SM_128_1  (4*((128*PITCH) + 1*(128*PITCH)))   // 49152
#define SM_64_2   (4*((64*PITCH)  + 2*(128*PITCH)))   // 61440
#define SM_64_1   (4*((64*PITCH)  + 1*(128*PITCH)))   // 36864

// ---------------- K6: gate final (fp16 Wg) ----------------
__global__ void __launch_bounds__(256) k_gate_final(const float* __restrict__ E,
                                                    const float* __restrict__ gbp,
                                                    const float* __restrict__ lw,
                                                    const float* __restrict__ lb){
  __shared__ float smA[128*68];
  __shared__ float ysig[BATCH*CTOT];
  __shared__ float bias[CTOT];
  int n = blockIdx.x, tid = threadIdx.x;

  float* Xs = smA;
  for(int t=tid; t<512; t+=256){
    ((float4*)Xs)[t]        = ((const float4*)(g_IAS + (size_t)n*BC))[t];
    ((float4*)(Xs+2048))[t] = ((const float4*)(g_XG1 + (size_t)n*BC))[t];
    ((float4*)(Xs+4096))[t] = ((const float4*)(g_XG2 + (size_t)n*BC))[t];
  }
  if(tid < CTOT){
    float b = 0.f;
    #pragma unroll
    for(int d=0; d<DEMB; d++) b += E[n*DEMB + d]*gbp[d*CTOT + tid];
    bias[tid] = b;
  }
  __syncthreads();

  int oq = (tid & 31)*4;
  int b0 = (tid >> 5)*2, b1 = b0 + 1;
  float acc[2][4];
  #pragma unroll
  for(int q=0;q<4;q++){ acc[0][q] = bias[oq+q]; acc[1][q] = bias[oq+q]; }

  const __half* W = g_Wg + (size_t)n*JG + oq;
  #pragma unroll
  for(int k=0; k<3; k++){
    const float* Xk0 = Xs + k*2048 + b0*CTOT;
    const float* Xk1 = Xs + k*2048 + b1*CTOT;
    const __half* Wk = W + (size_t)k*128*CTOT;
    #pragma unroll 8
    for(int i=0; i<128; i++){
      uint2 wv = *(const uint2*)(Wk + (size_t)i*CTOT);
      float2 f0 = __half22float2(*(__half2*)&wv.x);
      float2 f1 = __half22float2(*(__half2*)&wv.y);
      float x0 = Xk0[i], x1 = Xk1[i];
      acc[0][0] += x0*f0.x; acc[0][1] += x0*f0.y; acc[0][2] += x0*f1.x; acc[0][3] += x0*f1.y;
      acc[1][0] += x1*f0.x; acc[1][1] += x1*f0.y; acc[1][2] += x1*f1.x; acc[1][3] += x1*f1.y;
    }
  }
  #pragma unroll
  for(int bb=0; bb<2; bb++){
    float4 v;
    v.x = 1.f/(1.f + expf(-acc[bb][0]));
    v.y = 1.f/(1.f + expf(-acc[bb][1]));
    v.z = 1.f/(1.f + expf(-acc[bb][2]));
    v.w = 1.f/(1.f + expf(-acc[bb][3]));
    *(float4*)(ysig + (b0+bb)*CTOT + oq) = v;
  }
  __syncthreads();

  float* lwT = smA;
  for(int t=tid; t<CO*CTOT; t+=256){ int c = t>>7, oo = t&127; lwT[oo*68 + c] = lw[t]; }
  __syncthreads();

  int c4  = (tid & 15)*4;
  int bg  = tid >> 4;
  float acc2[4];
  #pragma unroll
  for(int q=0;q<4;q++) acc2[q] = lb[c4+q];
  const float* Ys = ysig + bg*CTOT;
  #pragma unroll 8
  for(int o2=0; o2<CTOT; o2++){
    float4 w4 = *(const float4*)(lwT + o2*68 + c4);
    float y = Ys[o2];
    acc2[0] += y*w4.x; acc2[1] += y*w4.y; acc2[2] += y*w4.z; acc2[3] += y*w4.w;
  }
  *(float4*)(g_Z + (size_t)n*BZ + bg*CO + c4) = make_float4(acc2[0],acc2[1],acc2[2],acc2[3]);
}

// ---------------- K9: upd final (fp16 Wu) ----------------
__global__ void __launch_bounds__(256) k_upd_final(const float* __restrict__ E,
                                                   const float* __restrict__ ubp,
                                                   float* __restrict__ out){
  __shared__ float Xs[3*1024];
  __shared__ float Zs[3*1024];
  __shared__ float bias[CO];
  int n = blockIdx.x, tid = threadIdx.x;
  {
    const float* s0 = g_IAS + (size_t)n*BC;
    const float* s1 = g_XG1 + (size_t)n*BC;
    const float* s2 = g_XG2 + (size_t)n*BC;
    int b = tid >> 4, f = (tid & 15)*4;
    ((float4*)(Xs       ))[tid] = *(const float4*)(s0 + b*CTOT + f);
    ((float4*)(Xs + 1024))[tid] = *(const float4*)(s1 + b*CTOT + f);
    ((float4*)(Xs + 2048))[tid] = *(const float4*)(s2 + b*CTOT + f);
    ((float4*)(Zs       ))[tid] = ((const float4*)(g_Z   + (size_t)n*BZ))[tid];
    ((float4*)(Zs + 1024))[tid] = ((const float4*)(g_ZG1 + (size_t)n*BZ))[tid];
    ((float4*)(Zs + 2048))[tid] = ((const float4*)(g_ZG2 + (size_t)n*BZ))[tid];
  }
  if(tid < CO){
    float b = 0.f;
    #pragma unroll
    for(int d=0; d<DEMB; d++) b += E[n*DEMB + d]*ubp[d*CO + tid];
    bias[tid] = b;
  }
  __syncthreads();

  int oq = (tid & 15)*4;
  int bg = tid >> 4;
  float acc[4];
  #pragma unroll
  for(int q=0;q<4;q++) acc[q] = bias[oq+q];

  const __half* W = g_Wu + (size_t)n*JU + oq;
  #pragma unroll
  for(int k=0; k<3; k++){
    const float* Xk = Xs + k*1024 + bg*CO;
    const float* Zk = Zs + k*1024 + bg*CO;
    const __half* Wk = W + (size_t)k*128*CO;
    #pragma unroll 8
    for(int i=0; i<64; i++){
      uint2 wv = *(const uint2*)(Wk + (size_t)i*CO);
      float2 f0 = __half22float2(*(__half2*)&wv.x);
      float2 f1 = __half22float2(*(__half2*)&wv.y);
      float x = Xk[i];
      acc[0] += x*f0.x; acc[1] += x*f0.y; acc[2] += x*f1.x; acc[3] += x*f1.y;
    }
    const __half* Wk2 = Wk + (size_t)64*CO;
    #pragma unroll 8
    for(int i=0; i<64; i++){
      uint2 wv = *(const uint2*)(Wk2 + (size_t)i*CO);
      float2 f0 = __half22float2(*(__half2*)&wv.x);
      float2 f1 = __half22float2(*(__half2*)&wv.y);
      float z = Zk[i];
      acc[0] += z*f0.x; acc[1] += z*f0.y; acc[2] += z*f1.x; acc[3] += z*f1.y;
    }
  }
  float4 v = make_float4(tanhf(acc[0]), tanhf(acc[1]), tanhf(acc[2]), tanhf(acc[3]));
  *(float4*)(out + ((size_t)bg*NN + n)*CO + oq) = v;
}

// ---------------- launch ----------------
extern "C" void kernel_launch(void* const* d_in, const int* in_sizes, int n_in,
                              void* d_out, int out_size){
  (void)in_sizes; (void)n_in; (void)out_size;
  const float* x   = (const float*)d_in[0];
  const float* st  = (const float*)d_in[1];
  const float* E   = (const float*)d_in[2];
  const float* gwp = (const float*)d_in[3];
  const float* gbp = (const float*)d_in[4];
  const float* uwp = (const float*)d_in[5];
  const float* ubp = (const float*)d_in[6];
  const float* lw  = (const float*)d_in[7];
  const float* lb  = (const float*)d_in[8];
  float* out = (float*)d_out;

  static cudaStream_t sSide = 0;
  static cudaEvent_t evFork = 0, evJoin = 0;
  static int init_done = 0;
  if(!init_done){
    cudaFuncSetAttribute(mma_gemm<0,1,128,2>, cudaFuncAttributeMaxDynamicSharedMemorySize, SM_128_2);
    cudaFuncSetAttribute(mma_gemm<1,0,128,1>, cudaFuncAttributeMaxDynamicSharedMemorySize, SM_128_1);
    cudaFuncSetAttribute(mma_gemm<0,1,64,2>,  cudaFuncAttributeMaxDynamicSharedMemorySize, SM_64_2);
    cudaFuncSetAttribute(mma_gemm<1,0,64,1>,  cudaFuncAttributeMaxDynamicSharedMemorySize, SM_64_1);
    cudaStreamCreateWithFlags(&sSide, cudaStreamNonBlocking);
    cudaEventCreateWithFlags(&evFork, cudaEventDisableTiming);
    cudaEventCreateWithFlags(&evJoin, cudaEventDisableTiming);
    init_done = 1;
  }

  k_supports<<<NN, 256>>>(E);
  k_pack<<<(NN*BC/4)/256, 256>>>(x, st);
  k_cvtT<<<dim3(BC/32, NN/32), 256>>>(0, BC, 0);                               // IAS -> Ta

  // launch 4 (profiled): big GEMM1 (2-product)
  mma_gemm<0,1,128,2><<<dim3(BC/128, NN/128), 256, SM_128_2>>>(1, 0, BC, 0, 2); // XG1; T->Tb

  cudaEventRecord(evFork, 0);
  cudaStreamWaitEvent(sSide, evFork, 0);
  k_wcombine<<<dim3(JG/1024, NN/32), 256, 0, sSide>>>(E, gwp, JG, 0);
  k_wcombine<<<dim3(JU/1024, NN/32), 256, 0, sSide>>>(E, uwp, JU, 1);
  cudaEventRecord(evJoin, sSide);

  // XG2 = 2*S@XG1 - IAS (1-product: error measured safe via R8 scaling)
  mma_gemm<1,0,128,1><<<dim3(BC/128, NN/128), 256, SM_128_1>>>(2, 0, BC, 2, 0);

  cudaStreamWaitEvent(0, evJoin, 0);
  k_gate_final<<<NN, 256>>>(E, gbp, lw, lb);                                   // -> g_Z

  k_cvtT<<<dim3(BZ/32, NN/32), 256>>>(3, BZ, 0);                               // Z -> Ta
  mma_gemm<0,1,64,2><<<dim3(BZ/128, NN/64), 256, SM_64_2>>>(4, 3, BZ, 0, 2);   // ZG1; T->Tb
  mma_gemm<1,0,64,1><<<dim3(BZ/128, NN/64), 256, SM_64_1>>>(5, 3, BZ, 2, 0);   // ZG2 (1-prod)

  k_upd_final<<<NN, 256>>>(E, ubp, out);                                       // -> hc
}

// round 17
// speedup vs baseline: 1.6257x; 1.0595x over previous
#include <cuda_runtime.h>
#include <cuda_fp16.h>
#include <math.h>
#include <stdint.h>

#define NN    2048
#define BATCH 16
#define DEMB  10
#define CTOT  128
#define CO    64
#define BC    (BATCH*CTOT)   // 2048
#define BZ    (BATCH*CO)     // 1024
#define KC    (3*CTOT)       // 384
#define JG    (KC*CTOT)      // 49152
#define JU    (KC*CO)        // 24576

// ---------------- device scratch ----------------
__device__ float g_IAS[(size_t)NN*BC];
__device__ float g_XG1[(size_t)NN*BC];
__device__ float g_XG2[(size_t)NN*BC];
__device__ float g_Z  [(size_t)NN*BZ];
__device__ float g_ZG1[(size_t)NN*BZ];
__device__ float g_ZG2[(size_t)NN*BZ];
__device__ __align__(256) __half g_Wg [(size_t)NN*JG];
__device__ __align__(256) __half g_Wu [(size_t)NN*JU];
__device__ __align__(256) __half g_Sh [(size_t)NN*NN];
__device__ __align__(256) __half g_TaH[(size_t)NN*NN];
__device__ __align__(256) __half g_TaL[(size_t)NN*NN];
__device__ __align__(256) __half g_TbH[(size_t)NN*NN];
__device__ __align__(256) __half g_TbL[(size_t)NN*NN];

// ---------------- pickers ----------------
__device__ __forceinline__ const float* pickIn(int id){
  switch(id){ case 0: return g_IAS; case 1: return g_XG1; case 2: return g_XG2;
              case 3: return g_Z;   case 4: return g_ZG1; }
  return g_IAS;
}
__device__ __forceinline__ float* pickOut(int id){
  switch(id){ case 1: return g_XG1; case 2: return g_XG2;
              case 4: return g_ZG1; case 5: return g_ZG2; }
  return g_XG1;
}
__device__ __forceinline__ __half* pickHF(int id){
  switch(id){ case 0: return g_TaH; case 1: return g_TaL;
              case 2: return g_TbH; case 3: return g_TbL; }
  return g_TaH;
}

// ---------------- warp reductions ----------------
__device__ __forceinline__ float warpMax(float v){
  #pragma unroll
  for(int o=16;o;o>>=1) v = fmaxf(v, __shfl_xor_sync(0xffffffffu, v, o));
  return v;
}
__device__ __forceinline__ float warpSum(float v){
  #pragma unroll
  for(int o=16;o;o>>=1) v += __shfl_xor_sync(0xffffffffu, v, o);
  return v;
}

// ---------------- PTX helpers ----------------
__device__ __forceinline__ uint32_t smem_u32(const void* p){
  uint32_t a;
  asm("{ .reg .u64 t; cvta.to.shared.u64 t, %1; cvt.u32.u64 %0, t; }" : "=r"(a) : "l"(p));
  return a;
}
__device__ __forceinline__ void cp16(uint32_t s, const void* g){
  asm volatile("cp.async.cg.shared.global [%0], [%1], 16;" :: "r"(s), "l"(g) : "memory");
}
__device__ __forceinline__ void cp_commit(){ asm volatile("cp.async.commit_group;" ::: "memory"); }
__device__ __forceinline__ void ldsm_x4(uint32_t* r, uint32_t a){
  asm volatile("ldmatrix.sync.aligned.m8n8.x4.shared.b16 {%0,%1,%2,%3}, [%4];"
    : "=r"(r[0]),"=r"(r[1]),"=r"(r[2]),"=r"(r[3]) : "r"(a));
}
__device__ __forceinline__ void mma16816(float* d, const uint32_t* a, const uint32_t* b){
  asm volatile("mma.sync.aligned.m16n8k16.row.col.f32.f16.f16.f32 "
    "{%0,%1,%2,%3}, {%4,%5,%6,%7}, {%8,%9}, {%0,%1,%2,%3};"
    : "+f"(d[0]),"+f"(d[1]),"+f"(d[2]),"+f"(d[3])
    : "r"(a[0]),"r"(a[1]),"r"(a[2]),"r"(a[3]), "r"(b[0]),"r"(b[1]));
}

// ---------------- K1: S row softmax -> fp16 ----------------
__global__ void __launch_bounds__(256) k_supports(const float* __restrict__ E){
  __shared__ float sh[8];
  __shared__ float bcast;
  int row = blockIdx.x, tid = threadIdx.x;
  float Er[DEMB];
  #pragma unroll
  for(int d=0; d<DEMB; d++) Er[d] = E[row*DEMB + d];
  float a[8], m = -1e30f;
  #pragma unroll
  for(int q=0; q<8; q++){
    int col = tid + q*256;
    const float* Ec = E + (size_t)col*DEMB;
    float s = 0.f;
    #pragma unroll
    for(int d=0; d<DEMB; d++) s += Er[d]*Ec[d];
    s = fmaxf(s, 0.f);
    a[q] = s; m = fmaxf(m, s);
  }
  m = warpMax(m);
  if((tid&31)==0) sh[tid>>5] = m;
  __syncthreads();
  if(tid<32){ float t = (tid<8)? sh[tid] : -1e30f; t = warpMax(t); if(tid==0) bcast = t; }
  __syncthreads();
  m = bcast;
  float ssum = 0.f;
  #pragma unroll
  for(int q=0; q<8; q++){ a[q] = expf(a[q]-m); ssum += a[q]; }
  ssum = warpSum(ssum);
  __syncthreads();
  if((tid&31)==0) sh[tid>>5] = ssum;
  __syncthreads();
  if(tid<32){ float t = (tid<8)? sh[tid] : 0.f; t = warpSum(t); if(tid==0) bcast = t; }
  __syncthreads();
  float inv = 1.f/bcast;
  #pragma unroll
  for(int q=0; q<8; q++)
    g_Sh[(size_t)row*NN + tid + q*256] = __float2half_rn(a[q]*inv);
}

// ---------------- K2: pack IAS ----------------
__global__ void __launch_bounds__(256) k_pack(const float* __restrict__ x,
                                              const float* __restrict__ st){
  int t = blockIdx.x*256 + threadIdx.x;
  int e = t*4;
  int n = e >> 11;
  int r = e & 2047;
  int b = r >> 7;
  int c = r & 127;
  float4 v;
  if (c < 64) v = *(const float4*)(x  + ((size_t)b*NN + n)*64 + c);
  else        v = *(const float4*)(st + ((size_t)b*NN + n)*64 + (c-64));
  *(float4*)(g_IAS + e) = v;
}

// -------- convert+transpose fp32 [2048 x W] -> fp16 hi (+opt lo) [W x 2048] --
template<int WLO>
__global__ void __launch_bounds__(256) k_cvtT(int srcId, int W, int dstHi){
  const float* src = pickIn(srcId);
  __half* dH = pickHF(dstHi);
  __half* dL = pickHF(dstHi+1);
  __shared__ float t[32][33];
  int tx = threadIdx.x & 31, ty = threadIdx.x >> 5;
  int c0 = blockIdx.x*32, r0 = blockIdx.y*32;
  #pragma unroll
  for(int j=0;j<4;j++)
    t[ty+8*j][tx] = src[(size_t)(r0+ty+8*j)*W + c0+tx];
  __syncthreads();
  #pragma unroll
  for(int j=0;j<4;j++){
    float v = t[tx][ty+8*j];
    __half hi = __float2half_rn(v);
    size_t o = (size_t)(c0+ty+8*j)*NN + r0 + tx;
    dH[o] = hi;
    if(WLO) dL[o] = __float2half_rn(v - __half2float(hi));
  }
}

// ---------------- K5: wcombine -> fp16 W ----------------
__global__ void __launch_bounds__(256) k_wcombine(const float* __restrict__ E,
                                                  const float* __restrict__ wp,
                                                  int J, int which){
  __half* out = which ? g_Wu : g_Wg;
  int j  = (blockIdx.x*256 + threadIdx.x)*4;
  int n0 = blockIdx.y*32;
  float4 w[DEMB];
  #pragma unroll
  for(int d=0; d<DEMB; d++) w[d] = *(const float4*)(wp + (size_t)d*J + j);
  __shared__ float Es[32*DEMB];
  for(int t=threadIdx.x; t<32*DEMB; t+=256) Es[t] = E[n0*DEMB + t];
  __syncthreads();
  #pragma unroll 2
  for(int nn=0; nn<32; nn++){
    float4 a = make_float4(0.f,0.f,0.f,0.f);
    #pragma unroll
    for(int d=0; d<DEMB; d++){
      float e = Es[nn*DEMB+d];
      a.x += e*w[d].x; a.y += e*w[d].y; a.z += e*w[d].z; a.w += e*w[d].w;
    }
    __half h[4];
    h[0] = __float2half_rn(a.x); h[1] = __float2half_rn(a.y);
    h[2] = __float2half_rn(a.z); h[3] = __float2half_rn(a.w);
    *(uint2*)(out + (size_t)(n0+nn)*J + j) = *(uint2*)h;
  }
}

// ---------------- HMMA fp16 GEMM, NPROD B-products ----------------
#define PITCH    48

template<int MODE, int WRITE_T, int TM, int NPROD>
__global__ void __launch_bounds__(256,2) mma_gemm(int cId, int dId, int Ncols,
                                                  int bHiId, int tHiId){
  constexpr int WM   = (TM == 128) ? 4 : 2;
  constexpr int WN   = 8 / WM;
  constexpr int NT   = (128 / WN) / 8;
  constexpr int NTP  = NT / 2;
  constexpr int A_T  = TM * PITCH;
  constexpr int B_T  = 128 * PITCH;
  constexpr int STG  = A_T + NPROD*B_T;
  constexpr int NTRANS = (TM + NPROD*128) * 2;
  constexpr int NU   = (NTRANS + 255) / 256;

  extern __shared__ char smem[];
  float*       C = pickOut(cId);
  const float* D = pickIn(dId);
  const __half* Bh = pickHF(bHiId);
  const __half* Bl = pickHF(bHiId+1);
  const uint32_t sb = smem_u32(smem);
  const int tid = threadIdx.x, wid = tid >> 5, lane = tid & 31;
  const int warpM = wid % WM, warpN = wid / WM;
  const size_t row0 = (size_t)blockIdx.y * TM;
  const size_t n0   = (size_t)blockIdx.x * 128;

  float acc[2][NT][4];
  #pragma unroll
  for(int m=0;m<2;m++)
    #pragma unroll
    for(int n=0;n<NT;n++)
      #pragma unroll
      for(int q=0;q<4;q++) acc[m][n][q] = 0.f;

  auto issue = [&](int c){
    const size_t kb = (size_t)c * 16;
    const uint32_t bo = sb + (uint32_t)(c & 3) * STG;
    #pragma unroll
    for(int u = 0; u < NU; u++){
      int e  = tid + u*256;
      if(NTRANS % 256 != 0 && e >= NTRANS) break;
      int h  = e & 1;
      int rr = e >> 1;
      if(rr < TM){
        cp16(bo + rr*PITCH + h*16, g_Sh + (row0 + rr)*(size_t)NN + kb + h*8);
      } else if(rr < TM + 128){
        int r = rr - TM;
        cp16(bo + A_T + r*PITCH + h*16, Bh + (n0 + r)*(size_t)NN + kb + h*8);
      } else if(NPROD == 2){
        int r = rr - TM - 128;
        cp16(bo + A_T + B_T + r*PITCH + h*16, Bl + (n0 + r)*(size_t)NN + kb + h*8);
      }
    }
    cp_commit();
  };

  issue(0); issue(1); issue(2);

  const uint32_t aoff = (uint32_t)((warpM*32 + (lane & 15))*PITCH + (lane >> 4)*16);
  const uint32_t boff = (uint32_t)(A_T + (warpN*(NT*8) + ((lane >> 4) & 1)*8 + (lane & 7))*PITCH
                                   + ((lane >> 3) & 1)*16);

  for(int c=0; c<128; c++){
    if(c <= 125)      asm volatile("cp.async.wait_group 2;" ::: "memory");
    else if(c == 126) asm volatile("cp.async.wait_group 1;" ::: "memory");
    else              asm volatile("cp.async.wait_group 0;" ::: "memory");
    __syncthreads();
    if(c + 3 < 128) issue(c+3);

    const uint32_t bo = sb + (uint32_t)(c & 3) * STG;
    uint32_t af[2][4];
    #pragma unroll
    for(int mt=0; mt<2; mt++)
      ldsm_x4(af[mt], bo + aoff + (uint32_t)(mt*16*PITCH));
    #pragma unroll
    for(int ntp=0; ntp<NTP; ntp++){
      uint32_t bd = bo + boff + (uint32_t)(ntp*16*PITCH);
      uint32_t bH[4];
      ldsm_x4(bH, bd);
      mma16816(acc[0][2*ntp],   af[0], bH);
      mma16816(acc[1][2*ntp],   af[1], bH);
      mma16816(acc[0][2*ntp+1], af[0], bH+2);
      mma16816(acc[1][2*ntp+1], af[1], bH+2);
      if(NPROD == 2){
        uint32_t bL[4];
        ldsm_x4(bL, bd + B_T);
        mma16816(acc[0][2*ntp],   af[0], bL);
        mma16816(acc[1][2*ntp],   af[1], bL);
        mma16816(acc[0][2*ntp+1], af[0], bL+2);
        mma16816(acc[1][2*ntp+1], af[1], bL+2);
      }
    }
  }

  // ---------------- epilogue ----------------
  const int g = lane >> 2, tg = lane & 3;
  #pragma unroll
  for(int mt=0; mt<2; mt++){
    size_t r0g = row0 + warpM*32 + mt*16 + g;
    #pragma unroll
    for(int nt=0; nt<NT; nt++){
      size_t col = n0 + warpN*(NT*8) + nt*8 + tg*2;
      size_t o0 = r0g      *(size_t)Ncols + col;
      size_t o1 = (r0g + 8)*(size_t)Ncols + col;
      float2 v0 = make_float2(acc[mt][nt][0], acc[mt][nt][1]);
      float2 v1 = make_float2(acc[mt][nt][2], acc[mt][nt][3]);
      if(MODE == 1){
        float2 d0 = *(const float2*)(D + o0);
        float2 d1 = *(const float2*)(D + o1);
        v0.x = 2.f*v0.x - d0.x; v0.y = 2.f*v0.y - d0.y;
        v1.x = 2.f*v1.x - d1.x; v1.y = 2.f*v1.y - d1.y;
      }
      *(float2*)(C + o0) = v0;
      *(float2*)(C + o1) = v1;
    }
  }

  if(WRITE_T){
    // downstream MODE1 GEMMs are 1-product: hi plane only
    __half* TH = pickHF(tHiId);
    float* tile = (float*)smem;          // [TM][132]
    __syncthreads();
    #pragma unroll
    for(int mt=0; mt<2; mt++){
      int rr = warpM*32 + mt*16 + g;
      #pragma unroll
      for(int nt=0; nt<NT; nt++){
        int cc = warpN*(NT*8) + nt*8 + tg*2;
        tile[rr*132 + cc]         = acc[mt][nt][0];
        tile[rr*132 + cc + 1]     = acc[mt][nt][1];
        tile[(rr+8)*132 + cc]     = acc[mt][nt][2];
        tile[(rr+8)*132 + cc + 1] = acc[mt][nt][3];
      }
    }
    __syncthreads();
    int c0 = tid >> 1, half_ = tid & 1;
    size_t baseO = (size_t)(n0 + c0)*NN + row0 + half_*(TM/2);
    #pragma unroll
    for(int ch=0; ch<TM/16; ch++){
      __half hb[8];
      #pragma unroll
      for(int e=0; e<8; e++)
        hb[e] = __float2half_rn(tile[(half_*(TM/2) + ch*8 + e)*132 + c0]);
      *(uint4*)(TH + baseO + ch*8) = *(uint4*)hb;
    }
  }
}

#define SM_128_2  (4*((128*PITCH) + 2*(128*PITCH)))   // 73728
#define SM_128_1  (4*((128*PITCH) + 1*(128*PITCH)))   // 49152
#define SM_64_1   (4*((64*PITCH)  + 1*(128*PITCH)))   // 36864

// ---------------- K6: gate final (fp16 Wg) ----------------
__global__ void __launch_bounds__(256) k_gate_final(const float* __restrict__ E,
                                                    const float* __restrict__ gbp,
                                                    const float* __restrict__ lw,
                                                    const float* __restrict__ lb){
  __shared__ float smA[128*68];
  __shared__ float ysig[BATCH*CTOT];
  __shared__ float bias[CTOT];
  int n = blockIdx.x, tid = threadIdx.x;

  float* Xs = smA;
  for(int t=tid; t<512; t+=256){
    ((float4*)Xs)[t]        = ((const float4*)(g_IAS + (size_t)n*BC))[t];
    ((float4*)(Xs+2048))[t] = ((const float4*)(g_XG1 + (size_t)n*BC))[t];
    ((float4*)(Xs+4096))[t] = ((const float4*)(g_XG2 + (size_t)n*BC))[t];
  }
  if(tid < CTOT){
    float b = 0.f;
    #pragma unroll
    for(int d=0; d<DEMB; d++) b += E[n*DEMB + d]*gbp[d*CTOT + tid];
    bias[tid] = b;
  }
  __syncthreads();

  int oq = (tid & 31)*4;
  int b0 = (tid >> 5)*2, b1 = b0 + 1;
  float acc[2][4];
  #pragma unroll
  for(int q=0;q<4;q++){ acc[0][q] = bias[oq+q]; acc[1][q] = bias[oq+q]; }

  const __half* W = g_Wg + (size_t)n*JG + oq;
  #pragma unroll
  for(int k=0; k<3; k++){
    const float* Xk0 = Xs + k*2048 + b0*CTOT;
    const float* Xk1 = Xs + k*2048 + b1*CTOT;
    const __half* Wk = W + (size_t)k*128*CTOT;
    #pragma unroll 8
    for(int i=0; i<128; i++){
      uint2 wv = *(const uint2*)(Wk + (size_t)i*CTOT);
      float2 f0 = __half22float2(*(__half2*)&wv.x);
      float2 f1 = __half22float2(*(__half2*)&wv.y);
      float x0 = Xk0[i], x1 = Xk1[i];
      acc[0][0] += x0*f0.x; acc[0][1] += x0*f0.y; acc[0][2] += x0*f1.x; acc[0][3] += x0*f1.y;
      acc[1][0] += x1*f0.x; acc[1][1] += x1*f0.y; acc[1][2] += x1*f1.x; acc[1][3] += x1*f1.y;
    }
  }
  #pragma unroll
  for(int bb=0; bb<2; bb++){
    float4 v;
    v.x = 1.f/(1.f + expf(-acc[bb][0]));
    v.y = 1.f/(1.f + expf(-acc[bb][1]));
    v.z = 1.f/(1.f + expf(-acc[bb][2]));
    v.w = 1.f/(1.f + expf(-acc[bb][3]));
    *(float4*)(ysig + (b0+bb)*CTOT + oq) = v;
  }
  __syncthreads();

  float* lwT = smA;
  for(int t=tid; t<CO*CTOT; t+=256){ int c = t>>7, oo = t&127; lwT[oo*68 + c] = lw[t]; }
  __syncthreads();

  int c4  = (tid & 15)*4;
  int bg  = tid >> 4;
  float acc2[4];
  #pragma unroll
  for(int q=0;q<4;q++) acc2[q] = lb[c4+q];
  const float* Ys = ysig + bg*CTOT;
  #pragma unroll 8
  for(int o2=0; o2<CTOT; o2++){
    float4 w4 = *(const float4*)(lwT + o2*68 + c4);
    float y = Ys[o2];
    acc2[0] += y*w4.x; acc2[1] += y*w4.y; acc2[2] += y*w4.z; acc2[3] += y*w4.w;
  }
  *(float4*)(g_Z + (size_t)n*BZ + bg*CO + c4) = make_float4(acc2[0],acc2[1],acc2[2],acc2[3]);
}

// ---------------- K9: upd final (fp16 Wu) ----------------
__global__ void __launch_bounds__(256) k_upd_final(const float* __restrict__ E,
                                                   const float* __restrict__ ubp,
                                                   float* __restrict__ out){
  __shared__ float Xs[3*1024];
  __shared__ float Zs[3*1024];
  __shared__ float bias[CO];
  int n = blockIdx.x, tid = threadIdx.x;
  {
    const float* s0 = g_IAS + (size_t)n*BC;
    const float* s1 = g_XG1 + (size_t)n*BC;
    const float* s2 = g_XG2 + (size_t)n*BC;
    int b = tid >> 4, f = (tid & 15)*4;
    ((float4*)(Xs       ))[tid] = *(const float4*)(s0 + b*CTOT + f);
    ((float4*)(Xs + 1024))[tid] = *(const float4*)(s1 + b*CTOT + f);
    ((float4*)(Xs + 2048))[tid] = *(const float4*)(s2 + b*CTOT + f);
    ((float4*)(Zs       ))[tid] = ((const float4*)(g_Z   + (size_t)n*BZ))[tid];
    ((float4*)(Zs + 1024))[tid] = ((const float4*)(g_ZG1 + (size_t)n*BZ))[tid];
    ((float4*)(Zs + 2048))[tid] = ((const float4*)(g_ZG2 + (size_t)n*BZ))[tid];
  }
  if(tid < CO){
    float b = 0.f;
    #pragma unroll
    for(int d=0; d<DEMB; d++) b += E[n*DEMB + d]*ubp[d*CO + tid];
    bias[tid] = b;
  }
  __syncthreads();

  int oq = (tid & 15)*4;
  int bg = tid >> 4;
  float acc[4];
  #pragma unroll
  for(int q=0;q<4;q++) acc[q] = bias[oq+q];

  const __half* W = g_Wu + (size_t)n*JU + oq;
  #pragma unroll
  for(int k=0; k<3; k++){
    const float* Xk = Xs + k*1024 + bg*CO;
    const float* Zk = Zs + k*1024 + bg*CO;
    const __half* Wk = W + (size_t)k*128*CO;
    #pragma unroll 8
    for(int i=0; i<64; i++){
      uint2 wv = *(const uint2*)(Wk + (size_t)i*CO);
      float2 f0 = __half22float2(*(__half2*)&wv.x);
      float2 f1 = __half22float2(*(__half2*)&wv.y);
      float x = Xk[i];
      acc[0] += x*f0.x; acc[1] += x*f0.y; acc[2] += x*f1.x; acc[3] += x*f1.y;
    }
    const __half* Wk2 = Wk + (size_t)64*CO;
    #pragma unroll 8
    for(int i=0; i<64; i++){
      uint2 wv = *(const uint2*)(Wk2 + (size_t)i*CO);
      float2 f0 = __half22float2(*(__half2*)&wv.x);
      float2 f1 = __half22float2(*(__half2*)&wv.y);
      float z = Zk[i];
      acc[0] += z*f0.x; acc[1] += z*f0.y; acc[2] += z*f1.x; acc[3] += z*f1.y;
    }
  }
  float4 v = make_float4(tanhf(acc[0]), tanhf(acc[1]), tanhf(acc[2]), tanhf(acc[3]));
  *(float4*)(out + ((size_t)bg*NN + n)*CO + oq) = v;
}

// ---------------- launch ----------------
extern "C" void kernel_launch(void* const* d_in, const int* in_sizes, int n_in,
                              void* d_out, int out_size){
  (void)in_sizes; (void)n_in; (void)out_size;
  const float* x   = (const float*)d_in[0];
  const float* st  = (const float*)d_in[1];
  const float* E   = (const float*)d_in[2];
  const float* gwp = (const float*)d_in[3];
  const float* gbp = (const float*)d_in[4];
  const float* uwp = (const float*)d_in[5];
  const float* ubp = (const float*)d_in[6];
  const float* lw  = (const float*)d_in[7];
  const float* lb  = (const float*)d_in[8];
  float* out = (float*)d_out;

  static cudaStream_t sSide = 0;
  static cudaEvent_t evFork = 0, evJoin = 0;
  static int init_done = 0;
  if(!init_done){
    cudaFuncSetAttribute(mma_gemm<0,1,128,2>, cudaFuncAttributeMaxDynamicSharedMemorySize, SM_128_2);
    cudaFuncSetAttribute(mma_gemm<1,0,128,1>, cudaFuncAttributeMaxDynamicSharedMemorySize, SM_128_1);
    cudaFuncSetAttribute(mma_gemm<0,1,64,1>,  cudaFuncAttributeMaxDynamicSharedMemorySize, SM_64_1);
    cudaFuncSetAttribute(mma_gemm<1,0,64,1>,  cudaFuncAttributeMaxDynamicSharedMemorySize, SM_64_1);
    cudaStreamCreateWithFlags(&sSide, cudaStreamNonBlocking);
    cudaEventCreateWithFlags(&evFork, cudaEventDisableTiming);
    cudaEventCreateWithFlags(&evJoin, cudaEventDisableTiming);
    init_done = 1;
  }

  k_supports<<<NN, 256>>>(E);
  k_pack<<<(NN*BC/4)/256, 256>>>(x, st);
  k_cvtT<1><<<dim3(BC/32, NN/32), 256>>>(0, BC, 0);                            // IAS -> Ta hi+lo

  // launch 4 (profiled): big GEMM1 (2-product)
  mma_gemm<0,1,128,2><<<dim3(BC/128, NN/128), 256, SM_128_2>>>(1, 0, BC, 0, 2); // XG1; T->TbH

  cudaEventRecord(evFork, 0);
  cudaStreamWaitEvent(sSide, evFork, 0);
  k_wcombine<<<dim3(JG/1024, NN/32), 256, 0, sSide>>>(E, gwp, JG, 0);
  k_wcombine<<<dim3(JU/1024, NN/32), 256, 0, sSide>>>(E, uwp, JU, 1);
  cudaEventRecord(evJoin, sSide);

  mma_gemm<1,0,128,1><<<dim3(BC/128, NN/128), 256, SM_128_1>>>(2, 0, BC, 2, 0); // XG2 (1-prod)

  cudaStreamWaitEvent(0, evJoin, 0);
  k_gate_final<<<NN, 256>>>(E, gbp, lw, lb);                                    // -> g_Z

  k_cvtT<0><<<dim3(BZ/32, NN/32), 256>>>(3, BZ, 0);                             // Z -> TaH only
  mma_gemm<0,1,64,1><<<dim3(BZ/128, NN/64), 256, SM_64_1>>>(4, 3, BZ, 0, 2);    // ZG1 (1-prod); T->TbH
  mma_gemm<1,0,64,1><<<dim3(BZ/128, NN/64), 256, SM_64_1>>>(5, 3, BZ, 2, 0);    // ZG2 (1-prod)

  k_upd_final<<<NN, 256>>>(E, ubp, out);                                        // -> hc
}